// round 1
// baseline (speedup 1.0000x reference)
#include <cuda_runtime.h>
#include <cuda_bf16.h>
#include <limits.h>

// Problem constants (fixed shapes from reference)
#define NN   10000
#define FIN  1024
#define HH   3
#define CC   1024
#define HC   (HH*CC)     // 3072
#define NCLS 460
#define EE   100000
#define ET   (EE+NN)     // edges + self-loops

// ---------------- scratch (device globals; no allocations allowed) ----------------
__device__ float g_xl[NN*HC];      // 123 MB
__device__ float g_xr[NN*HC];      // 123 MB
__device__ float g_agg[NN*HC];     // 123 MB
__device__ float g_h[NN*CC];       // 41 MB
__device__ float g_score[ET*HH];
__device__ float g_escore[ET*HH];
__device__ int   g_smax[NN*HH];
__device__ float g_denom[NN*HH];
__device__ int   g_is64;           // 1 if edge_index is int64, 0 if int32

// ---------------- helpers ----------------
__device__ __forceinline__ int f2ord(float f) {
    int i = __float_as_int(f);
    return (i >= 0) ? i : (i ^ 0x7FFFFFFF);
}
__device__ __forceinline__ float ord2f(int i) {
    return __int_as_float((i >= 0) ? i : (i ^ 0x7FFFFFFF));
}

// Fetch (src, dst) for edge e; e >= EE are self-loops.
__device__ __forceinline__ void edge_sd(const void* ei, int e, int& s, int& d) {
    if (e >= EE) { s = d = e - EE; return; }
    if (g_is64) {
        const long long* p = (const long long*)ei;
        s = (int)p[2*e]; d = (int)p[2*e+1];
    } else {
        const int* p = (const int*)ei;
        s = p[2*e]; d = p[2*e+1];
    }
}

// ---------------- dtype detection for edge_index ----------------
// If int64 (little-endian), high 32-bit words of values < 10000 are all zero.
// If int32, odd words are dst values — essentially never all zero over 2048 pairs.
__global__ void detect_idx_kernel(const int* ei) {
    __shared__ int any_nz;
    if (threadIdx.x == 0) any_nz = 0;
    __syncthreads();
    for (int i = threadIdx.x; i < 2048; i += blockDim.x) {
        if (ei[2*i + 1] != 0) any_nz = 1;   // benign race: only writes 1
    }
    __syncthreads();
    if (threadIdx.x == 0) g_is64 = (any_nz == 0) ? 1 : 0;
}

// ---------------- SGEMM: C[M,N] = A[M,K] @ B[K,N] + bias[N] ----------------
__global__ __launch_bounds__(256, 2)
void sgemm_bias(int M, int N, int K,
                const float* __restrict__ A, const float* __restrict__ B,
                const float* __restrict__ bias, float* __restrict__ C) {
    constexpr int BM = 128, BN = 128, BK = 8, TM = 8, TN = 8;
    __shared__ float As[BK][BM];
    __shared__ float Bs[BK][BN];
    const int tid  = threadIdx.x;
    const int brow = blockIdx.y * BM;
    const int bcol = blockIdx.x * BN;
    const int tcol = tid % 16;
    const int trow = tid / 16;

    float acc[TM][TN];
    #pragma unroll
    for (int i = 0; i < TM; i++)
        #pragma unroll
        for (int j = 0; j < TN; j++) acc[i][j] = 0.0f;

    for (int k0 = 0; k0 < K; k0 += BK) {
        // Load A tile (BM x BK)
        #pragma unroll
        for (int l = tid; l < BM*BK; l += 256) {
            int m = l / BK, k = l % BK;
            int gr = brow + m;
            As[k][m] = (gr < M) ? A[(long)gr * K + k0 + k] : 0.0f;
        }
        // Load B tile (BK x BN)
        #pragma unroll
        for (int l = tid; l < BK*BN; l += 256) {
            int k = l / BN, n = l % BN;
            int gc = bcol + n;
            Bs[k][n] = (gc < N) ? B[(long)(k0 + k) * N + gc] : 0.0f;
        }
        __syncthreads();
        #pragma unroll
        for (int k = 0; k < BK; k++) {
            float ra[TM], rb[TN];
            #pragma unroll
            for (int i = 0; i < TM; i++) ra[i] = As[k][trow*TM + i];
            #pragma unroll
            for (int j = 0; j < TN; j++) rb[j] = Bs[k][tcol*TN + j];
            #pragma unroll
            for (int i = 0; i < TM; i++)
                #pragma unroll
                for (int j = 0; j < TN; j++) acc[i][j] += ra[i] * rb[j];
        }
        __syncthreads();
    }

    #pragma unroll
    for (int i = 0; i < TM; i++) {
        int r = brow + trow*TM + i;
        if (r >= M) continue;
        #pragma unroll
        for (int j = 0; j < TN; j++) {
            int c = bcol + tcol*TN + j;
            if (c < N) C[(long)r * N + c] = acc[i][j] + bias[c];
        }
    }
}

// ---------------- init scratch (must run every launch: graph replays) ----------------
__global__ void init_kernel() {
    int i = blockIdx.x * blockDim.x + threadIdx.x;
    int stride = gridDim.x * blockDim.x;
    for (int j = i; j < NN*HC; j += stride) g_agg[j] = 0.0f;
    for (int j = i; j < NN*HH; j += stride) { g_smax[j] = INT_MIN; g_denom[j] = 0.0f; }
}

// ---------------- edge scores: one warp per (edge, head) ----------------
__global__ void edge_score_kernel(const void* __restrict__ ei, const float* __restrict__ att) {
    int gw   = (blockIdx.x * blockDim.x + threadIdx.x) >> 5;
    int lane = threadIdx.x & 31;
    if (gw >= ET*HH) return;
    int e = gw / HH, h = gw % HH;
    int s, d; edge_sd(ei, e, s, d);
    const float* pl = &g_xl[(long)s*HC + h*CC];
    const float* pr = &g_xr[(long)d*HC + h*CC];
    const float* pa = &att[h*CC];
    float acc = 0.0f;
    #pragma unroll 4
    for (int c = lane; c < CC; c += 32) {
        float v = pl[c] + pr[c];
        v = (v > 0.0f) ? v : 0.2f * v;   // leaky_relu, slope 0.2
        acc += __ldg(&pa[c]) * v;
    }
    #pragma unroll
    for (int o = 16; o; o >>= 1) acc += __shfl_xor_sync(0xFFFFFFFF, acc, o);
    if (lane == 0) g_score[e*HH + h] = acc;
}

// ---------------- segment max over dst ----------------
__global__ void seg_max_kernel(const void* __restrict__ ei) {
    int t = blockIdx.x * blockDim.x + threadIdx.x;
    if (t >= ET*HH) return;
    int e = t / HH, h = t % HH;
    int s, d; edge_sd(ei, e, s, d);
    atomicMax(&g_smax[d*HH + h], f2ord(g_score[t]));
}

// ---------------- exp(score - max), segment sum ----------------
__global__ void escore_kernel(const void* __restrict__ ei) {
    int t = blockIdx.x * blockDim.x + threadIdx.x;
    if (t >= ET*HH) return;
    int e = t / HH, h = t % HH;
    int s, d; edge_sd(ei, e, s, d);
    float m  = ord2f(g_smax[d*HH + h]);
    float es = expf(g_score[t] - m);
    g_escore[t] = es;
    atomicAdd(&g_denom[d*HH + h], es);
}

// ---------------- aggregate: one warp per (edge, head) ----------------
__global__ void aggregate_kernel(const void* __restrict__ ei) {
    int gw   = (blockIdx.x * blockDim.x + threadIdx.x) >> 5;
    int lane = threadIdx.x & 31;
    if (gw >= ET*HH) return;
    int e = gw / HH, h = gw % HH;
    int s, d; edge_sd(ei, e, s, d);
    float alpha = g_escore[e*HH + h] / (g_denom[d*HH + h] + 1e-16f);
    const float* pl = &g_xl[(long)s*HC + h*CC];
    float*       po = &g_agg[(long)d*HC + h*CC];
    #pragma unroll 4
    for (int c = lane; c < CC; c += 32)
        atomicAdd(&po[c], alpha * pl[c]);
}

// ---------------- head mean + conv bias ----------------
__global__ void headmean_kernel(const float* __restrict__ bias) {
    int t = blockIdx.x * blockDim.x + threadIdx.x;
    if (t >= NN*CC) return;
    int i = t / CC, c = t % CC;
    const float* p = &g_agg[(long)i*HC];
    g_h[t] = (p[c] + p[CC + c] + p[2*CC + c]) * (1.0f/3.0f) + bias[c];
}

// ---------------- launch ----------------
extern "C" void kernel_launch(void* const* d_in, const int* in_sizes, int n_in,
                              void* d_out, int out_size) {
    const float* x      = (const float*)d_in[0];
    const void*  ei     = d_in[1];
    const float* Wl     = (const float*)d_in[2];
    const float* bl     = (const float*)d_in[3];
    const float* Wr     = (const float*)d_in[4];
    const float* br     = (const float*)d_in[5];
    const float* att    = (const float*)d_in[6];
    const float* bias   = (const float*)d_in[7];
    const float* Wfc    = (const float*)d_in[8];
    const float* bfc    = (const float*)d_in[9];
    const float* exps   = (const float*)d_in[10];
    const float* exps_c = (const float*)d_in[11];
    float* out = (float*)d_out;

    float *p_xl, *p_xr, *p_h;
    cudaGetSymbolAddress((void**)&p_xl, g_xl);
    cudaGetSymbolAddress((void**)&p_xr, g_xr);
    cudaGetSymbolAddress((void**)&p_h,  g_h);

    detect_idx_kernel<<<1, 256>>>((const int*)ei);

    dim3 gProj((HC + 127) / 128, (NN + 127) / 128);   // 24 x 79
    sgemm_bias<<<gProj, 256>>>(NN, HC, FIN, x, Wl, bl, p_xl);
    sgemm_bias<<<gProj, 256>>>(NN, HC, FIN, x, Wr, br, p_xr);

    init_kernel<<<2048, 256>>>();

    const int nTasks = ET * HH;                       // 330000
    const int warpBlocks   = (nTasks * 32 + 255) / 256;
    const int threadBlocks = (nTasks + 255) / 256;

    edge_score_kernel<<<warpBlocks, 256>>>(ei, att);
    seg_max_kernel<<<threadBlocks, 256>>>(ei);
    escore_kernel<<<threadBlocks, 256>>>(ei);
    aggregate_kernel<<<warpBlocks, 256>>>(ei);
    headmean_kernel<<<(NN*CC + 255) / 256, 256>>>(bias);

    dim3 gFc((NCLS + 127) / 128, (NN + 127) / 128);   // 4 x 79
    sgemm_bias<<<gFc, 256>>>(NN, NCLS, CC, p_h, Wfc, bfc, out);

    // Pass-throughs: (h, exps, exps_c) concatenated in the output buffer.
    long off = (long)NN * NCLS;
    if (n_in >= 12 && (long)out_size >= off + in_sizes[10] + in_sizes[11]) {
        cudaMemcpyAsync(out + off, exps, (size_t)in_sizes[10] * sizeof(float),
                        cudaMemcpyDeviceToDevice);
        cudaMemcpyAsync(out + off + in_sizes[10], exps_c,
                        (size_t)in_sizes[11] * sizeof(float),
                        cudaMemcpyDeviceToDevice);
    }
}

// round 5
// speedup vs baseline: 2.1560x; 2.1560x over previous
#include <cuda_runtime.h>
#include <cuda_bf16.h>
#include <cstdint>
#include <limits.h>

// Problem constants
#define NN   10000
#define FIN  1024
#define HH   3
#define CC   1024
#define HC   (HH*CC)     // 3072
#define NCLS 460
#define EE   100000
#define ET   (EE+NN)
#define MPAD 10112       // 79 * 128

// ---------------- scratch (device globals) ----------------
__device__ float g_xl[NN*HC];
__device__ float g_xr[NN*HC];
__device__ float g_agg[NN*HC];
__device__ float g_h[NN*CC];
__device__ float g_score[ET*HH];
__device__ float g_escore[ET*HH];
__device__ int   g_smax[NN*HH];
__device__ float g_denom[NN*HH];
__device__ int   g_is64;

// split-bf16 operands
__device__ __nv_bfloat16 g_xh[MPAD*FIN];
__device__ __nv_bfloat16 g_xlo[MPAD*FIN];
__device__ __nv_bfloat16 g_wth[2][HC*FIN];   // W^T hi  [N=HC][K=FIN]
__device__ __nv_bfloat16 g_wtl[2][HC*FIN];   // W^T lo

// ---------------- small helpers ----------------
__device__ __forceinline__ int f2ord(float f) {
    int i = __float_as_int(f);
    return (i >= 0) ? i : (i ^ 0x7FFFFFFF);
}
__device__ __forceinline__ float ord2f(int i) {
    return __int_as_float((i >= 0) ? i : (i ^ 0x7FFFFFFF));
}
__device__ __forceinline__ void edge_sd(const void* ei, int e, int& s, int& d) {
    if (e >= EE) { s = d = e - EE; return; }
    if (g_is64) {
        const long long* p = (const long long*)ei;
        s = (int)p[2*e]; d = (int)p[2*e+1];
    } else {
        const int* p = (const int*)ei;
        s = p[2*e]; d = p[2*e+1];
    }
}
__device__ __forceinline__ uint32_t smem_u32(const void* p) {
    uint32_t a;
    asm("{ .reg .u64 t; cvta.to.shared.u64 t, %1; cvt.u32.u64 %0, t; }" : "=r"(a) : "l"(p));
    return a;
}

#define CP_ASYNC16(dst, src) \
    asm volatile("cp.async.cg.shared.global [%0], [%1], 16;" :: "r"(dst), "l"(src))
#define CP_COMMIT() asm volatile("cp.async.commit_group;" ::: "memory")
#define CP_WAIT(n)  asm volatile("cp.async.wait_group %0;" :: "n"(n) : "memory")

#define LDSM_X4(r0, r1, r2, r3, addr) \
    asm volatile("ldmatrix.sync.aligned.m8n8.x4.shared.b16 {%0,%1,%2,%3}, [%4];" \
        : "=r"(r0), "=r"(r1), "=r"(r2), "=r"(r3) : "r"(addr))

#define MMA16816(d, a, b) \
    asm volatile("mma.sync.aligned.m16n8k16.row.col.f32.bf16.bf16.f32 " \
        "{%0,%1,%2,%3},{%4,%5,%6,%7},{%8,%9},{%0,%1,%2,%3};" \
        : "+f"((d)[0]), "+f"((d)[1]), "+f"((d)[2]), "+f"((d)[3]) \
        : "r"((a)[0]), "r"((a)[1]), "r"((a)[2]), "r"((a)[3]), "r"((b)[0]), "r"((b)[1]))

// XOR swizzle for a 128-row x 64-byte tile: conflict-free ldmatrix + stores
__device__ __forceinline__ uint32_t tileoff(int row, int chunk) {
    return (uint32_t)(row * 64 + ((chunk ^ ((row >> 1) & 3)) << 4));
}

__global__ void detect_idx_kernel(const int* ei) {
    __shared__ int any_nz;
    if (threadIdx.x == 0) any_nz = 0;
    __syncthreads();
    for (int i = threadIdx.x; i < 2048; i += blockDim.x)
        if (ei[2*i + 1] != 0) any_nz = 1;
    __syncthreads();
    if (threadIdx.x == 0) g_is64 = (any_nz == 0) ? 1 : 0;
}

// ---------------- split-bf16 conversion ----------------
__global__ void convert_x_kernel(const float* __restrict__ x) {
    int stride = gridDim.x * blockDim.x;
    for (int i = blockIdx.x * blockDim.x + threadIdx.x; i < MPAD*FIN; i += stride) {
        int row = i >> 10;
        float v = (row < NN) ? x[i] : 0.0f;
        __nv_bfloat16 h = __float2bfloat16(v);
        g_xh[i]  = h;
        g_xlo[i] = __float2bfloat16(v - __bfloat162float(h));
    }
}

__global__ void convert_w_kernel(const float* __restrict__ W,
                                 __nv_bfloat16* __restrict__ Th,
                                 __nv_bfloat16* __restrict__ Tl) {
    __shared__ float t[32][33];
    int n0 = blockIdx.x * 32, k0 = blockIdx.y * 32;
    int tx = threadIdx.x, ty = threadIdx.y;
    #pragma unroll
    for (int j = 0; j < 32; j += 8)
        t[ty + j][tx] = W[(long)(k0 + ty + j) * HC + n0 + tx];
    __syncthreads();
    #pragma unroll
    for (int j = 0; j < 32; j += 8) {
        float v = t[tx][ty + j];
        __nv_bfloat16 h = __float2bfloat16(v);
        long o = (long)(n0 + ty + j) * FIN + k0 + tx;
        Th[o] = h;
        Tl[o] = __float2bfloat16(v - __bfloat162float(h));
    }
}

// ---------------- mma.sync split-bf16 GEMM ----------------
// C[M=10000(pad 10112), N=3072] = x @ W + bias; 3-term split accumulation.
// grid (24, 79), 256 threads, 64KB dynamic smem (2 stages x 4 tiles x 8KB).
#define NKI (FIN/32)      // 32 k-iters
#define SMEM_MMA (2*4*8192)

__global__ __launch_bounds__(256, 2)
void mma_gemm_kernel(const __nv_bfloat16* __restrict__ Bh_g,
                     const __nv_bfloat16* __restrict__ Bl_g,
                     const float* __restrict__ bias, float* __restrict__ C) {
    extern __shared__ char smem[];
    const uint32_t sbase = smem_u32(smem);
    const int tid = threadIdx.x, lane = tid & 31, wid = tid >> 5;
    const int wm = (wid >> 1) * 32, wn = (wid & 1) * 64;
    const int m0 = blockIdx.y * 128, n0 = blockIdx.x * 128;

    const __nv_bfloat16* srcs[4] = {
        g_xh  + (size_t)m0 * FIN,
        g_xlo + (size_t)m0 * FIN,
        Bh_g  + (size_t)n0 * FIN,
        Bl_g  + (size_t)n0 * FIN
    };

    float acc[2][8][4];
    #pragma unroll
    for (int i = 0; i < 2; i++)
        #pragma unroll
        for (int j = 0; j < 8; j++)
            #pragma unroll
            for (int k = 0; k < 4; k++) acc[i][j][k] = 0.0f;

    // --- async stage loader: 4 tiles (Ah, Al, Bh, Bl), each 128x32 bf16 ---
    auto issue = [&](int it) {
        const int s = it & 1, k0 = it * 32;
        #pragma unroll
        for (int i = 0; i < 8; i++) {
            int idx = tid + i * 256;
            int tile = idx >> 9, w = idx & 511, row = w >> 2, ch = w & 3;
            const void* g = (const void*)(srcs[tile] + (size_t)row * FIN + k0 + ch * 8);
            uint32_t d = sbase + s * 32768 + tile * 8192 + tileoff(row, ch);
            CP_ASYNC16(d, g);
        }
        CP_COMMIT();
    };

    issue(0);

    for (int it = 0; it < NKI; it++) {
        if (it + 1 < NKI) { issue(it + 1); CP_WAIT(1); }
        else              { CP_WAIT(0); }
        __syncthreads();
        const uint32_t st = sbase + (it & 1) * 32768;

        #pragma unroll
        for (int ks = 0; ks < 2; ks++) {
            // A fragments: 2 m-tiles x (hi, lo)
            uint32_t ah[2][4], al[2][4];
            #pragma unroll
            for (int mt = 0; mt < 2; mt++) {
                int row = wm + mt * 16 + (lane & 15);
                int ch  = ks * 2 + (lane >> 4);
                uint32_t off = tileoff(row, ch);
                LDSM_X4(ah[mt][0], ah[mt][1], ah[mt][2], ah[mt][3], st + off);
                LDSM_X4(al[mt][0], al[mt][1], al[mt][2], al[mt][3], st + 8192 + off);
            }
            #pragma unroll
            for (int nh = 0; nh < 2; nh++) {
                // B fragments: 4 n-tiles (two x4 loads) x (hi, lo)
                uint32_t bh[4][2], bl[4][2];
                #pragma unroll
                for (int np = 0; np < 2; np++) {
                    int row = wn + nh * 32 + np * 16 + ((lane >> 4) << 3) + (lane & 7);
                    int ch  = ks * 2 + ((lane >> 3) & 1);
                    uint32_t off = tileoff(row, ch);
                    LDSM_X4(bh[np*2][0], bh[np*2][1], bh[np*2+1][0], bh[np*2+1][1],
                            st + 16384 + off);
                    LDSM_X4(bl[np*2][0], bl[np*2][1], bl[np*2+1][0], bl[np*2+1][1],
                            st + 24576 + off);
                }
                #pragma unroll
                for (int mt = 0; mt < 2; mt++)
                    #pragma unroll
                    for (int nt = 0; nt < 4; nt++) {
                        float* d = acc[mt][nh*4 + nt];
                        MMA16816(d, ah[mt], bh[nt]);
                        MMA16816(d, ah[mt], bl[nt]);
                        MMA16816(d, al[mt], bh[nt]);
                    }
            }
        }
        __syncthreads();
    }

    // epilogue: direct fp32 stores + bias
    const int g4 = lane >> 2, t4 = lane & 3;
    #pragma unroll
    for (int mt = 0; mt < 2; mt++) {
        #pragma unroll
        for (int nt = 0; nt < 8; nt++) {
            int col = n0 + wn + nt * 8 + t4 * 2;
            float b0 = bias[col], b1 = bias[col + 1];
            int r0 = m0 + wm + mt * 16 + g4;
            float* d = acc[mt][nt];
            if (r0 < NN) {
                float2 v = make_float2(d[0] + b0, d[1] + b1);
                *(float2*)&C[(size_t)r0 * HC + col] = v;
            }
            if (r0 + 8 < NN) {
                float2 v = make_float2(d[2] + b0, d[3] + b1);
                *(float2*)&C[(size_t)(r0 + 8) * HC + col] = v;
            }
        }
    }
}

// ---------------- fp32 SIMT SGEMM (FC readout) ----------------
__global__ __launch_bounds__(256, 2)
void sgemm_bias(int M, int N, int K,
                const float* __restrict__ A, const float* __restrict__ B,
                const float* __restrict__ bias, float* __restrict__ C) {
    constexpr int BM = 128, BN = 128, BK = 8, TM = 8, TN = 8;
    __shared__ float As[BK][BM];
    __shared__ float Bs[BK][BN];
    const int tid = threadIdx.x;
    const int brow = blockIdx.y * BM, bcol = blockIdx.x * BN;
    const int tcol = tid % 16, trow = tid / 16;
    float acc[TM][TN];
    #pragma unroll
    for (int i = 0; i < TM; i++)
        #pragma unroll
        for (int j = 0; j < TN; j++) acc[i][j] = 0.0f;
    for (int k0 = 0; k0 < K; k0 += BK) {
        #pragma unroll
        for (int l = tid; l < BM*BK; l += 256) {
            int mm = l / BK, k = l % BK;
            int gr = brow + mm;
            As[k][mm] = (gr < M) ? A[(long)gr * K + k0 + k] : 0.0f;
        }
        #pragma unroll
        for (int l = tid; l < BK*BN; l += 256) {
            int k = l / BN, n = l % BN;
            int gc = bcol + n;
            Bs[k][n] = (gc < N) ? B[(long)(k0 + k) * N + gc] : 0.0f;
        }
        __syncthreads();
        #pragma unroll
        for (int k = 0; k < BK; k++) {
            float ra[TM], rb[TN];
            #pragma unroll
            for (int i = 0; i < TM; i++) ra[i] = As[k][trow*TM + i];
            #pragma unroll
            for (int j = 0; j < TN; j++) rb[j] = Bs[k][tcol*TN + j];
            #pragma unroll
            for (int i = 0; i < TM; i++)
                #pragma unroll
                for (int j = 0; j < TN; j++) acc[i][j] += ra[i] * rb[j];
        }
        __syncthreads();
    }
    #pragma unroll
    for (int i = 0; i < TM; i++) {
        int r = brow + trow*TM + i;
        if (r >= M) continue;
        #pragma unroll
        for (int j = 0; j < TN; j++) {
            int c = bcol + tcol*TN + j;
            if (c < N) C[(long)r * N + c] = acc[i][j] + bias[c];
        }
    }
}

// ---------------- init scratch ----------------
__global__ void init_kernel() {
    int i = blockIdx.x * blockDim.x + threadIdx.x;
    int stride = gridDim.x * blockDim.x;
    for (int j = i; j < NN*HC; j += stride) g_agg[j] = 0.0f;
    for (int j = i; j < NN*HH; j += stride) { g_smax[j] = INT_MIN; g_denom[j] = 0.0f; }
}

// ---------------- edge scores + fused segment max ----------------
__global__ void edge_score_kernel(const void* __restrict__ ei, const float* __restrict__ att) {
    int gw = (blockIdx.x * blockDim.x + threadIdx.x) >> 5;
    int lane = threadIdx.x & 31;
    if (gw >= ET*HH) return;
    int e = gw / HH, h = gw % HH;
    int s, d; edge_sd(ei, e, s, d);
    const float* pl = &g_xl[(long)s*HC + h*CC];
    const float* pr = &g_xr[(long)d*HC + h*CC];
    const float* pa = &att[h*CC];
    float acc = 0.0f;
    #pragma unroll 4
    for (int c = lane; c < CC; c += 32) {
        float v = pl[c] + pr[c];
        v = (v > 0.0f) ? v : 0.2f * v;
        acc += __ldg(&pa[c]) * v;
    }
    #pragma unroll
    for (int o = 16; o; o >>= 1) acc += __shfl_xor_sync(0xFFFFFFFF, acc, o);
    if (lane == 0) {
        g_score[e*HH + h] = acc;
        atomicMax(&g_smax[d*HH + h], f2ord(acc));
    }
}

// ---------------- exp(score - max), segment sum ----------------
__global__ void escore_kernel(const void* __restrict__ ei) {
    int t = blockIdx.x * blockDim.x + threadIdx.x;
    if (t >= ET*HH) return;
    int e = t / HH, h = t % HH;
    int s, d; edge_sd(ei, e, s, d);
    float m = ord2f(g_smax[d*HH + h]);
    float es = expf(g_score[t] - m);
    g_escore[t] = es;
    atomicAdd(&g_denom[d*HH + h], es);
}

// ---------------- aggregate ----------------
__global__ void aggregate_kernel(const void* __restrict__ ei) {
    int gw = (blockIdx.x * blockDim.x + threadIdx.x) >> 5;
    int lane = threadIdx.x & 31;
    if (gw >= ET*HH) return;
    int e = gw / HH, h = gw % HH;
    int s, d; edge_sd(ei, e, s, d);
    float alpha = g_escore[e*HH + h] / (g_denom[d*HH + h] + 1e-16f);
    const float* pl = &g_xl[(long)s*HC + h*CC];
    float*       po = &g_agg[(long)d*HC + h*CC];
    #pragma unroll 4
    for (int c = lane; c < CC; c += 32)
        atomicAdd(&po[c], alpha * pl[c]);
}

// ---------------- head mean + conv bias ----------------
__global__ void headmean_kernel(const float* __restrict__ bias) {
    int t = blockIdx.x * blockDim.x + threadIdx.x;
    if (t >= NN*CC) return;
    int i = t / CC, c = t % CC;
    const float* p = &g_agg[(long)i*HC];
    g_h[t] = (p[c] + p[CC + c] + p[2*CC + c]) * (1.0f/3.0f) + bias[c];
}

// ---------------- launch ----------------
extern "C" void kernel_launch(void* const* d_in, const int* in_sizes, int n_in,
                              void* d_out, int out_size) {
    const float* x      = (const float*)d_in[0];
    const void*  ei     = d_in[1];
    const float* Wl     = (const float*)d_in[2];
    const float* bl     = (const float*)d_in[3];
    const float* Wr     = (const float*)d_in[4];
    const float* br     = (const float*)d_in[5];
    const float* att    = (const float*)d_in[6];
    const float* bias   = (const float*)d_in[7];
    const float* Wfc    = (const float*)d_in[8];
    const float* bfc    = (const float*)d_in[9];
    const float* exps   = (const float*)d_in[10];
    const float* exps_c = (const float*)d_in[11];
    float* out = (float*)d_out;

    float *p_xl, *p_xr, *p_h;
    __nv_bfloat16 *p_wth0, *p_wtl0, *p_wth1, *p_wtl1;
    cudaGetSymbolAddress((void**)&p_xl, g_xl);
    cudaGetSymbolAddress((void**)&p_xr, g_xr);
    cudaGetSymbolAddress((void**)&p_h,  g_h);
    {
        __nv_bfloat16* base_h; __nv_bfloat16* base_l;
        cudaGetSymbolAddress((void**)&base_h, g_wth);
        cudaGetSymbolAddress((void**)&base_l, g_wtl);
        p_wth0 = base_h;                   p_wtl0 = base_l;
        p_wth1 = base_h + (size_t)HC*FIN;  p_wtl1 = base_l + (size_t)HC*FIN;
    }

    cudaFuncSetAttribute(mma_gemm_kernel, cudaFuncAttributeMaxDynamicSharedMemorySize, SMEM_MMA);

    detect_idx_kernel<<<1, 256>>>((const int*)ei);
    convert_x_kernel<<<2048, 256>>>(x);
    {
        dim3 gw(HC/32, FIN/32), bw(32, 8);
        convert_w_kernel<<<gw, bw>>>(Wl, p_wth0, p_wtl0);
        convert_w_kernel<<<gw, bw>>>(Wr, p_wth1, p_wtl1);
    }
    init_kernel<<<2048, 256>>>();

    dim3 gG(HC/128, MPAD/128);  // 24 x 79
    mma_gemm_kernel<<<gG, 256, SMEM_MMA>>>(p_wth0, p_wtl0, bl, p_xl);
    mma_gemm_kernel<<<gG, 256, SMEM_MMA>>>(p_wth1, p_wtl1, br, p_xr);

    const int nTasks = ET * HH;
    const int warpBlocks   = (nTasks * 32 + 255) / 256;
    const int threadBlocks = (nTasks + 255) / 256;
    edge_score_kernel<<<warpBlocks, 256>>>(ei, att);
    escore_kernel<<<threadBlocks, 256>>>(ei);
    aggregate_kernel<<<warpBlocks, 256>>>(ei);
    headmean_kernel<<<(NN*CC + 255) / 256, 256>>>(bias);

    dim3 gFc((NCLS + 127) / 128, (NN + 127) / 128);
    sgemm_bias<<<gFc, 256>>>(NN, NCLS, CC, p_h, Wfc, bfc, out);

    long off = (long)NN * NCLS;
    if (n_in >= 12 && (long)out_size >= off + in_sizes[10] + in_sizes[11]) {
        cudaMemcpyAsync(out + off, exps, (size_t)in_sizes[10] * sizeof(float),
                        cudaMemcpyDeviceToDevice);
        cudaMemcpyAsync(out + off + in_sizes[10], exps_c,
                        (size_t)in_sizes[11] * sizeof(float),
                        cudaMemcpyDeviceToDevice);
    }
}

// round 6
// speedup vs baseline: 3.5663x; 1.6541x over previous
#include <cuda_runtime.h>
#include <cuda_bf16.h>
#include <cstdint>
#include <limits.h>

// Problem constants
#define NN   10000
#define FIN  1024
#define HH   3
#define CC   1024
#define HC   (HH*CC)     // 3072
#define NCLS 460
#define EE   100000
#define MPAD 10112       // 79 * 128
#define SC_MAX 352       // max per-node in-degree+1 supported (actual ~36)

// ---------------- scratch (device globals) ----------------
__device__ float g_xl[NN*HC];
__device__ float g_xr[NN*HC];
__device__ float g_h[NN*CC];
__device__ int   g_is64;

// CSR
__device__ int g_deg[NN];
__device__ int g_off[NN];
__device__ int g_cursor[NN];
__device__ int g_srcs[EE];

// split-bf16 operands
__device__ __nv_bfloat16 g_xh[MPAD*FIN];
__device__ __nv_bfloat16 g_xlo[MPAD*FIN];
__device__ __nv_bfloat16 g_wth[2][HC*FIN];   // W^T hi  [N=HC][K=FIN]
__device__ __nv_bfloat16 g_wtl[2][HC*FIN];   // W^T lo
__device__ __nv_bfloat16 g_wfch[512*FIN];    // Wfc^T hi (zero-padded to 512 rows)
__device__ __nv_bfloat16 g_wfcl[512*FIN];    // Wfc^T lo

// ---------------- small helpers ----------------
__device__ __forceinline__ void edge_sd(const void* ei, int e, int& s, int& d) {
    if (g_is64) {
        const long long* p = (const long long*)ei;
        s = (int)p[2*e]; d = (int)p[2*e+1];
    } else {
        const int* p = (const int*)ei;
        s = p[2*e]; d = p[2*e+1];
    }
}
__device__ __forceinline__ uint32_t smem_u32(const void* p) {
    uint32_t a;
    asm("{ .reg .u64 t; cvta.to.shared.u64 t, %1; cvt.u32.u64 %0, t; }" : "=r"(a) : "l"(p));
    return a;
}

#define CP_ASYNC16(dst, src) \
    asm volatile("cp.async.cg.shared.global [%0], [%1], 16;" :: "r"(dst), "l"(src))
#define CP_COMMIT() asm volatile("cp.async.commit_group;" ::: "memory")
#define CP_WAIT(n)  asm volatile("cp.async.wait_group %0;" :: "n"(n) : "memory")

#define LDSM_X4(r0, r1, r2, r3, addr) \
    asm volatile("ldmatrix.sync.aligned.m8n8.x4.shared.b16 {%0,%1,%2,%3}, [%4];" \
        : "=r"(r0), "=r"(r1), "=r"(r2), "=r"(r3) : "r"(addr))

#define MMA16816(d, a, b) \
    asm volatile("mma.sync.aligned.m16n8k16.row.col.f32.bf16.bf16.f32 " \
        "{%0,%1,%2,%3},{%4,%5,%6,%7},{%8,%9},{%0,%1,%2,%3};" \
        : "+f"((d)[0]), "+f"((d)[1]), "+f"((d)[2]), "+f"((d)[3]) \
        : "r"((a)[0]), "r"((a)[1]), "r"((a)[2]), "r"((a)[3]), "r"((b)[0]), "r"((b)[1]))

__device__ __forceinline__ uint32_t tileoff(int row, int chunk) {
    return (uint32_t)(row * 64 + ((chunk ^ ((row >> 1) & 3)) << 4));
}

__global__ void detect_idx_kernel(const int* ei) {
    __shared__ int any_nz;
    if (threadIdx.x == 0) any_nz = 0;
    __syncthreads();
    for (int i = threadIdx.x; i < 2048; i += blockDim.x)
        if (ei[2*i + 1] != 0) any_nz = 1;
    __syncthreads();
    if (threadIdx.x == 0) g_is64 = (any_nz == 0) ? 1 : 0;
}

// ---------------- CSR build ----------------
__global__ void zero_deg_kernel() {
    int i = blockIdx.x * blockDim.x + threadIdx.x;
    if (i < NN) g_deg[i] = 0;
}
__global__ void histo_kernel(const void* __restrict__ ei) {
    int e = blockIdx.x * blockDim.x + threadIdx.x;
    if (e >= EE) return;
    int s, d; edge_sd(ei, e, s, d);
    atomicAdd(&g_deg[d], 1);
}
__global__ void scan_kernel() {   // single block, 1024 threads
    __shared__ int s_warp[32];
    __shared__ int s_carry;
    int tid = threadIdx.x, lane = tid & 31, w = tid >> 5;
    if (tid == 0) s_carry = 0;
    __syncthreads();
    for (int base = 0; base < NN; base += 1024) {
        int idx = base + tid;
        int v = (idx < NN) ? g_deg[idx] : 0;
        int x = v;
        #pragma unroll
        for (int o = 1; o < 32; o <<= 1) {
            int y = __shfl_up_sync(0xFFFFFFFF, x, o);
            if (lane >= o) x += y;
        }
        if (lane == 31) s_warp[w] = x;
        __syncthreads();
        if (w == 0) {
            int y = s_warp[lane];
            #pragma unroll
            for (int o = 1; o < 32; o <<= 1) {
                int z = __shfl_up_sync(0xFFFFFFFF, y, o);
                if (lane >= o) y += z;
            }
            s_warp[lane] = y;
        }
        __syncthreads();
        int incl = x + (w > 0 ? s_warp[w - 1] : 0);
        int excl = incl - v + s_carry;
        if (idx < NN) { g_off[idx] = excl; g_cursor[idx] = excl; }
        __syncthreads();
        if (tid == 1023) s_carry += incl;
        __syncthreads();
    }
}
__global__ void scatter_kernel(const void* __restrict__ ei) {
    int e = blockIdx.x * blockDim.x + threadIdx.x;
    if (e >= EE) return;
    int s, d; edge_sd(ei, e, s, d);
    int pos = atomicAdd(&g_cursor[d], 1);
    g_srcs[pos] = s;
}

// ---------------- split-bf16 conversion ----------------
__global__ void convert_x_kernel(const float* __restrict__ x) {
    int stride = gridDim.x * blockDim.x;
    for (int i = blockIdx.x * blockDim.x + threadIdx.x; i < MPAD*FIN; i += stride) {
        int row = i >> 10;
        float v = (row < NN) ? x[i] : 0.0f;
        __nv_bfloat16 h = __float2bfloat16(v);
        g_xh[i]  = h;
        g_xlo[i] = __float2bfloat16(v - __bfloat162float(h));
    }
}

// transpose + split W [K=1024, N] -> Wt [Npad][1024] hi/lo; zero rows >= N
__global__ void convert_w_kernel(const float* __restrict__ W, int N,
                                 __nv_bfloat16* __restrict__ Th,
                                 __nv_bfloat16* __restrict__ Tl) {
    __shared__ float t[32][33];
    int n0 = blockIdx.x * 32, k0 = blockIdx.y * 32;
    int tx = threadIdx.x, ty = threadIdx.y;
    #pragma unroll
    for (int j = 0; j < 32; j += 8) {
        int n = n0 + tx;
        t[ty + j][tx] = (n < N) ? W[(long)(k0 + ty + j) * N + n] : 0.0f;
    }
    __syncthreads();
    #pragma unroll
    for (int j = 0; j < 32; j += 8) {
        float v = t[tx][ty + j];
        __nv_bfloat16 h = __float2bfloat16(v);
        long o = (long)(n0 + ty + j) * FIN + k0 + tx;
        Th[o] = h;
        Tl[o] = __float2bfloat16(v - __bfloat162float(h));
    }
}

// ---------------- mma.sync split-bf16 GEMM ----------------
// C[M=10000, ncols<=ldc] = A(g_xh/g_xlo) @ B^T + bias; 3-term split accumulation.
#define NKI (FIN/32)
#define SMEM_MMA (2*4*8192)

__global__ __launch_bounds__(256, 2)
void mma_gemm_kernel(const __nv_bfloat16* __restrict__ Bh_g,
                     const __nv_bfloat16* __restrict__ Bl_g,
                     const float* __restrict__ bias, float* __restrict__ C,
                     int ldc, int nmax) {
    extern __shared__ char smem[];
    const uint32_t sbase = smem_u32(smem);
    const int tid = threadIdx.x, lane = tid & 31, wid = tid >> 5;
    const int wm = (wid >> 1) * 32, wn = (wid & 1) * 64;
    const int m0 = blockIdx.y * 128, n0 = blockIdx.x * 128;

    const __nv_bfloat16* srcs[4] = {
        g_xh  + (size_t)m0 * FIN,
        g_xlo + (size_t)m0 * FIN,
        Bh_g  + (size_t)n0 * FIN,
        Bl_g  + (size_t)n0 * FIN
    };

    float acc[2][8][4];
    #pragma unroll
    for (int i = 0; i < 2; i++)
        #pragma unroll
        for (int j = 0; j < 8; j++)
            #pragma unroll
            for (int k = 0; k < 4; k++) acc[i][j][k] = 0.0f;

    auto issue = [&](int it) {
        const int s = it & 1, k0 = it * 32;
        #pragma unroll
        for (int i = 0; i < 8; i++) {
            int idx = tid + i * 256;
            int tile = idx >> 9, w = idx & 511, row = w >> 2, ch = w & 3;
            const void* g = (const void*)(srcs[tile] + (size_t)row * FIN + k0 + ch * 8);
            uint32_t d = sbase + s * 32768 + tile * 8192 + tileoff(row, ch);
            CP_ASYNC16(d, g);
        }
        CP_COMMIT();
    };

    issue(0);

    for (int it = 0; it < NKI; it++) {
        if (it + 1 < NKI) { issue(it + 1); CP_WAIT(1); }
        else              { CP_WAIT(0); }
        __syncthreads();
        const uint32_t st = sbase + (it & 1) * 32768;

        #pragma unroll
        for (int ks = 0; ks < 2; ks++) {
            uint32_t ah[2][4], al[2][4];
            #pragma unroll
            for (int mt = 0; mt < 2; mt++) {
                int row = wm + mt * 16 + (lane & 15);
                int ch  = ks * 2 + (lane >> 4);
                uint32_t off = tileoff(row, ch);
                LDSM_X4(ah[mt][0], ah[mt][1], ah[mt][2], ah[mt][3], st + off);
                LDSM_X4(al[mt][0], al[mt][1], al[mt][2], al[mt][3], st + 8192 + off);
            }
            #pragma unroll
            for (int nh = 0; nh < 2; nh++) {
                uint32_t bh[4][2], bl[4][2];
                #pragma unroll
                for (int np = 0; np < 2; np++) {
                    int row = wn + nh * 32 + np * 16 + ((lane >> 4) << 3) + (lane & 7);
                    int ch  = ks * 2 + ((lane >> 3) & 1);
                    uint32_t off = tileoff(row, ch);
                    LDSM_X4(bh[np*2][0], bh[np*2][1], bh[np*2+1][0], bh[np*2+1][1],
                            st + 16384 + off);
                    LDSM_X4(bl[np*2][0], bl[np*2][1], bl[np*2+1][0], bl[np*2+1][1],
                            st + 24576 + off);
                }
                #pragma unroll
                for (int mt = 0; mt < 2; mt++)
                    #pragma unroll
                    for (int nt = 0; nt < 4; nt++) {
                        float* d = acc[mt][nh*4 + nt];
                        MMA16816(d, ah[mt], bh[nt]);
                        MMA16816(d, ah[mt], bl[nt]);
                        MMA16816(d, al[mt], bh[nt]);
                    }
            }
        }
        __syncthreads();
    }

    const int g4 = lane >> 2, t4 = lane & 3;
    #pragma unroll
    for (int mt = 0; mt < 2; mt++) {
        #pragma unroll
        for (int nt = 0; nt < 8; nt++) {
            int col = n0 + wn + nt * 8 + t4 * 2;
            if (col >= nmax) continue;
            float b0 = bias[col], b1 = bias[col + 1];
            int r0 = m0 + wm + mt * 16 + g4;
            float* d = acc[mt][nt];
            if (r0 < NN) {
                float2 v = make_float2(d[0] + b0, d[1] + b1);
                *(float2*)&C[(size_t)r0 * ldc + col] = v;
            }
            if (r0 + 8 < NN) {
                float2 v = make_float2(d[2] + b0, d[3] + b1);
                *(float2*)&C[(size_t)(r0 + 8) * ldc + col] = v;
            }
        }
    }
}

// ---------------- fused per-node edge phase ----------------
// One block (256 threads) per node: scores -> softmax -> aggregate+mean+bias.
__global__ __launch_bounds__(256)
void node_fused_kernel(const float* __restrict__ att, const float* __restrict__ bias) {
    __shared__ float s_xr[HC];
    __shared__ float s_att[HC];
    __shared__ float s_sc[HH][SC_MAX];

    const int i = blockIdx.x;
    const int tid = threadIdx.x, lane = tid & 31, wid = tid >> 5;
    const int deg = g_deg[i], off = g_off[i];
    int ecnt = deg + 1;                 // + self-loop (last slot)
    if (ecnt > SC_MAX) ecnt = SC_MAX;   // never happens for this data

    // load xr row and att into smem
    #pragma unroll
    for (int c = tid; c < HC; c += 256) {
        s_xr[c]  = g_xr[(size_t)i * HC + c];
        s_att[c] = att[c];
    }
    __syncthreads();

    // scores: warp per (edge, head) pair
    const int npairs = ecnt * HH;
    for (int p = wid; p < npairs; p += 8) {
        int e = p / HH, h = p % HH;
        int src = (e < deg) ? g_srcs[off + e] : i;
        const float* xlrow = g_xl + (size_t)src * HC + h * CC;
        const float* xr_h  = s_xr + h * CC;
        const float* at_h  = s_att + h * CC;
        float acc = 0.0f;
        #pragma unroll 4
        for (int c = lane; c < CC; c += 32) {
            float v = xlrow[c] + xr_h[c];
            v = (v > 0.0f) ? v : 0.2f * v;
            acc += at_h[c] * v;
        }
        #pragma unroll
        for (int o = 16; o; o >>= 1) acc += __shfl_xor_sync(0xFFFFFFFF, acc, o);
        if (lane == 0) s_sc[h][e] = acc;
    }
    __syncthreads();

    // softmax per head (warps 0..2)
    if (wid < HH) {
        float m = -1e30f;
        for (int e = lane; e < ecnt; e += 32) m = fmaxf(m, s_sc[wid][e]);
        #pragma unroll
        for (int o = 16; o; o >>= 1) m = fmaxf(m, __shfl_xor_sync(0xFFFFFFFF, m, o));
        float sum = 0.0f;
        for (int e = lane; e < ecnt; e += 32) {
            float ex = expf(s_sc[wid][e] - m);
            s_sc[wid][e] = ex;
            sum += ex;
        }
        #pragma unroll
        for (int o = 16; o; o >>= 1) sum += __shfl_xor_sync(0xFFFFFFFF, sum, o);
        float inv = 1.0f / (sum + 1e-16f);
        for (int e = lane; e < ecnt; e += 32) s_sc[wid][e] *= inv;
    }
    __syncthreads();

    // aggregate + head mean + bias: thread owns channels tid, tid+256, tid+512, tid+768
    float a0 = 0.0f, a1 = 0.0f, a2 = 0.0f, a3 = 0.0f;
    for (int e = 0; e < ecnt; e++) {
        int src = (e < deg) ? g_srcs[off + e] : i;
        const float* base = g_xl + (size_t)src * HC;
        #pragma unroll
        for (int h = 0; h < HH; h++) {
            float al = s_sc[h][e];
            const float* row = base + h * CC;
            a0 += al * row[tid];
            a1 += al * row[tid + 256];
            a2 += al * row[tid + 512];
            a3 += al * row[tid + 768];
        }
    }
    const float third = 1.0f / 3.0f;
    float* ho = g_h + (size_t)i * CC;
    ho[tid]       = a0 * third + bias[tid];
    ho[tid + 256] = a1 * third + bias[tid + 256];
    ho[tid + 512] = a2 * third + bias[tid + 512];
    ho[tid + 768] = a3 * third + bias[tid + 768];
}

// convert h -> split bf16 (reuses g_xh/g_xlo; K = CC = 1024)
__global__ void convert_h_kernel() {
    int stride = gridDim.x * blockDim.x;
    for (int i = blockIdx.x * blockDim.x + threadIdx.x; i < MPAD*CC; i += stride) {
        int row = i >> 10;
        float v = (row < NN) ? g_h[i] : 0.0f;
        __nv_bfloat16 h = __float2bfloat16(v);
        g_xh[i]  = h;
        g_xlo[i] = __float2bfloat16(v - __bfloat162float(h));
    }
}

// ---------------- launch ----------------
extern "C" void kernel_launch(void* const* d_in, const int* in_sizes, int n_in,
                              void* d_out, int out_size) {
    const float* x      = (const float*)d_in[0];
    const void*  ei     = d_in[1];
    const float* Wl     = (const float*)d_in[2];
    const float* bl     = (const float*)d_in[3];
    const float* Wr     = (const float*)d_in[4];
    const float* br     = (const float*)d_in[5];
    const float* att    = (const float*)d_in[6];
    const float* bias   = (const float*)d_in[7];
    const float* Wfc    = (const float*)d_in[8];
    const float* bfc    = (const float*)d_in[9];
    const float* exps   = (const float*)d_in[10];
    const float* exps_c = (const float*)d_in[11];
    float* out = (float*)d_out;

    float *p_xl, *p_xr;
    __nv_bfloat16 *p_wth, *p_wtl, *p_wfch, *p_wfcl;
    cudaGetSymbolAddress((void**)&p_xl, g_xl);
    cudaGetSymbolAddress((void**)&p_xr, g_xr);
    cudaGetSymbolAddress((void**)&p_wth, g_wth);
    cudaGetSymbolAddress((void**)&p_wtl, g_wtl);
    cudaGetSymbolAddress((void**)&p_wfch, g_wfch);
    cudaGetSymbolAddress((void**)&p_wfcl, g_wfcl);

    cudaFuncSetAttribute(mma_gemm_kernel, cudaFuncAttributeMaxDynamicSharedMemorySize, SMEM_MMA);

    detect_idx_kernel<<<1, 256>>>((const int*)ei);

    // CSR build
    zero_deg_kernel<<<(NN + 255) / 256, 256>>>();
    histo_kernel<<<(EE + 255) / 256, 256>>>(ei);
    scan_kernel<<<1, 1024>>>();
    scatter_kernel<<<(EE + 255) / 256, 256>>>(ei);

    // split-bf16 conversions
    convert_x_kernel<<<2048, 256>>>(x);
    {
        dim3 bw(32, 8);
        convert_w_kernel<<<dim3(HC/32, FIN/32), bw>>>(Wl, HC, p_wth, p_wtl);
        convert_w_kernel<<<dim3(HC/32, FIN/32), bw>>>(Wr, HC,
            p_wth + (size_t)HC*FIN, p_wtl + (size_t)HC*FIN);
        convert_w_kernel<<<dim3(512/32, CC/32), bw>>>(Wfc, NCLS, p_wfch, p_wfcl);
    }

    // projection GEMMs (tensor cores)
    dim3 gG(HC/128, MPAD/128);
    mma_gemm_kernel<<<gG, 256, SMEM_MMA>>>(p_wth, p_wtl, bl, p_xl, HC, HC);
    mma_gemm_kernel<<<gG, 256, SMEM_MMA>>>(p_wth + (size_t)HC*FIN, p_wtl + (size_t)HC*FIN,
                                           br, p_xr, HC, HC);

    // fused edge phase (scores -> softmax -> aggregate -> head mean -> +bias)
    node_fused_kernel<<<NN, 256>>>(att, bias);

    // FC readout on tensor cores
    convert_h_kernel<<<2048, 256>>>();
    mma_gemm_kernel<<<dim3(512/128, MPAD/128), 256, SMEM_MMA>>>(
        p_wfch, p_wfcl, bfc, out, NCLS, NCLS);

    // pass-throughs
    long off = (long)NN * NCLS;
    if (n_in >= 12 && (long)out_size >= off + in_sizes[10] + in_sizes[11]) {
        cudaMemcpyAsync(out + off, exps, (size_t)in_sizes[10] * sizeof(float),
                        cudaMemcpyDeviceToDevice);
        cudaMemcpyAsync(out + off + in_sizes[10], exps_c,
                        (size_t)in_sizes[11] * sizeof(float),
                        cudaMemcpyDeviceToDevice);
    }
}

// round 7
// speedup vs baseline: 3.6805x; 1.0320x over previous
#include <cuda_runtime.h>
#include <cuda_bf16.h>
#include <cstdint>
#include <limits.h>

// Problem constants
#define NN   10000
#define FIN  1024
#define HH   3
#define CC   1024
#define HC   (HH*CC)     // 3072
#define NCLS 460
#define EE   100000
#define MPAD 10112       // 79 * 128
#define SC_MAX 352

// ---------------- scratch (device globals) ----------------
__device__ float g_xl[NN*HC];
__device__ float g_xr[NN*HC];
__device__ float g_h[NN*CC];
__device__ int   g_is64;

// CSR
__device__ int g_deg[NN];
__device__ int g_off[NN];
__device__ int g_cursor[NN];
__device__ int g_srcs[EE];

// split-bf16 operands
__device__ __nv_bfloat16 g_xh[MPAD*FIN];
__device__ __nv_bfloat16 g_xlo[MPAD*FIN];
__device__ __nv_bfloat16 g_wth[2][HC*FIN];   // W^T hi: [Wl^T ; Wr^T] contiguous (6144 x 1024)
__device__ __nv_bfloat16 g_wtl[2][HC*FIN];   // W^T lo
__device__ __nv_bfloat16 g_wfch[512*FIN];    // Wfc^T hi (zero-padded to 512 rows)
__device__ __nv_bfloat16 g_wfcl[512*FIN];    // Wfc^T lo

// ---------------- small helpers ----------------
__device__ __forceinline__ void edge_sd(const void* ei, int e, int& s, int& d) {
    if (g_is64) {
        const long long* p = (const long long*)ei;
        s = (int)p[2*e]; d = (int)p[2*e+1];
    } else {
        const int* p = (const int*)ei;
        s = p[2*e]; d = p[2*e+1];
    }
}
__device__ __forceinline__ uint32_t smem_u32(const void* p) {
    uint32_t a;
    asm("{ .reg .u64 t; cvta.to.shared.u64 t, %1; cvt.u32.u64 %0, t; }" : "=r"(a) : "l"(p));
    return a;
}

#define CP_ASYNC16(dst, src) \
    asm volatile("cp.async.cg.shared.global [%0], [%1], 16;" :: "r"(dst), "l"(src))
#define CP_COMMIT() asm volatile("cp.async.commit_group;" ::: "memory")
#define CP_WAIT(n)  asm volatile("cp.async.wait_group %0;" :: "n"(n) : "memory")

#define LDSM_X4(r0, r1, r2, r3, addr) \
    asm volatile("ldmatrix.sync.aligned.m8n8.x4.shared.b16 {%0,%1,%2,%3}, [%4];" \
        : "=r"(r0), "=r"(r1), "=r"(r2), "=r"(r3) : "r"(addr))

#define MMA16816(d, a, b) \
    asm volatile("mma.sync.aligned.m16n8k16.row.col.f32.bf16.bf16.f32 " \
        "{%0,%1,%2,%3},{%4,%5,%6,%7},{%8,%9},{%0,%1,%2,%3};" \
        : "+f"((d)[0]), "+f"((d)[1]), "+f"((d)[2]), "+f"((d)[3]) \
        : "r"((a)[0]), "r"((a)[1]), "r"((a)[2]), "r"((a)[3]), "r"((b)[0]), "r"((b)[1]))

__device__ __forceinline__ uint32_t tileoff(int row, int chunk) {
    return (uint32_t)(row * 64 + ((chunk ^ ((row >> 1) & 3)) << 4));
}

__global__ void detect_idx_kernel(const int* ei) {
    __shared__ int any_nz;
    if (threadIdx.x == 0) any_nz = 0;
    __syncthreads();
    for (int i = threadIdx.x; i < 2048; i += blockDim.x)
        if (ei[2*i + 1] != 0) any_nz = 1;
    __syncthreads();
    if (threadIdx.x == 0) g_is64 = (any_nz == 0) ? 1 : 0;
}

// ---------------- CSR build ----------------
__global__ void zero_deg_kernel() {
    int i = blockIdx.x * blockDim.x + threadIdx.x;
    if (i < NN) g_deg[i] = 0;
}
__global__ void histo_kernel(const void* __restrict__ ei) {
    int e = blockIdx.x * blockDim.x + threadIdx.x;
    if (e >= EE) return;
    int s, d; edge_sd(ei, e, s, d);
    atomicAdd(&g_deg[d], 1);
}
__global__ void scan_kernel() {   // single block, 1024 threads
    __shared__ int s_warp[32];
    __shared__ int s_carry;
    int tid = threadIdx.x, lane = tid & 31, w = tid >> 5;
    if (tid == 0) s_carry = 0;
    __syncthreads();
    for (int base = 0; base < NN; base += 1024) {
        int idx = base + tid;
        int v = (idx < NN) ? g_deg[idx] : 0;
        int x = v;
        #pragma unroll
        for (int o = 1; o < 32; o <<= 1) {
            int y = __shfl_up_sync(0xFFFFFFFF, x, o);
            if (lane >= o) x += y;
        }
        if (lane == 31) s_warp[w] = x;
        __syncthreads();
        if (w == 0) {
            int y = s_warp[lane];
            #pragma unroll
            for (int o = 1; o < 32; o <<= 1) {
                int z = __shfl_up_sync(0xFFFFFFFF, y, o);
                if (lane >= o) y += z;
            }
            s_warp[lane] = y;
        }
        __syncthreads();
        int incl = x + (w > 0 ? s_warp[w - 1] : 0);
        int excl = incl - v + s_carry;
        if (idx < NN) { g_off[idx] = excl; g_cursor[idx] = excl; }
        __syncthreads();
        if (tid == 1023) s_carry += incl;
        __syncthreads();
    }
}
__global__ void scatter_kernel(const void* __restrict__ ei) {
    int e = blockIdx.x * blockDim.x + threadIdx.x;
    if (e >= EE) return;
    int s, d; edge_sd(ei, e, s, d);
    int pos = atomicAdd(&g_cursor[d], 1);
    g_srcs[pos] = s;
}

// ---------------- split-bf16 conversion ----------------
__global__ void convert_x_kernel(const float* __restrict__ x) {
    int stride = gridDim.x * blockDim.x;
    for (int i = blockIdx.x * blockDim.x + threadIdx.x; i < MPAD*FIN; i += stride) {
        int row = i >> 10;
        float v = (row < NN) ? x[i] : 0.0f;
        __nv_bfloat16 h = __float2bfloat16(v);
        g_xh[i]  = h;
        g_xlo[i] = __float2bfloat16(v - __bfloat162float(h));
    }
}

// transpose + split W [K=1024, N] -> Wt [Npad][1024] hi/lo; zero rows >= N
__global__ void convert_w_kernel(const float* __restrict__ W, int N,
                                 __nv_bfloat16* __restrict__ Th,
                                 __nv_bfloat16* __restrict__ Tl) {
    __shared__ float t[32][33];
    int n0 = blockIdx.x * 32, k0 = blockIdx.y * 32;
    int tx = threadIdx.x, ty = threadIdx.y;
    #pragma unroll
    for (int j = 0; j < 32; j += 8) {
        int n = n0 + tx;
        t[ty + j][tx] = (n < N) ? W[(long)(k0 + ty + j) * N + n] : 0.0f;
    }
    __syncthreads();
    #pragma unroll
    for (int j = 0; j < 32; j += 8) {
        float v = t[tx][ty + j];
        __nv_bfloat16 h = __float2bfloat16(v);
        long o = (long)(n0 + ty + j) * FIN + k0 + tx;
        Th[o] = h;
        Tl[o] = __float2bfloat16(v - __bfloat162float(h));
    }
}

// ---------------- mma.sync split-bf16 GEMM, 3-stage pipeline ----------------
// A = (g_xh, g_xlo) [MPAD x 1024].  B^T rows n; columns < nsplit go to C0/bias0,
// columns >= nsplit go to C1/bias1 (col - nsplit).  nmax = valid cols per side.
#define NKI (FIN/32)
#define SMEM_MMA (3*4*8192)   // 3 stages x 4 tiles x 8KB = 96KB

__global__ __launch_bounds__(256, 2)
void mma_gemm_kernel(const __nv_bfloat16* __restrict__ Bh_g,
                     const __nv_bfloat16* __restrict__ Bl_g,
                     const float* __restrict__ bias0, const float* __restrict__ bias1,
                     float* __restrict__ C0, float* __restrict__ C1,
                     int ldc, int nmax, int nsplit) {
    extern __shared__ char smem[];
    const uint32_t sbase = smem_u32(smem);
    const int tid = threadIdx.x, lane = tid & 31, wid = tid >> 5;
    const int wm = (wid >> 1) * 32, wn = (wid & 1) * 64;
    const int m0 = blockIdx.y * 128, n0 = blockIdx.x * 128;

    const __nv_bfloat16* srcs[4] = {
        g_xh  + (size_t)m0 * FIN,
        g_xlo + (size_t)m0 * FIN,
        Bh_g  + (size_t)n0 * FIN,
        Bl_g  + (size_t)n0 * FIN
    };

    float acc[2][8][4];
    #pragma unroll
    for (int i = 0; i < 2; i++)
        #pragma unroll
        for (int j = 0; j < 8; j++)
            #pragma unroll
            for (int k = 0; k < 4; k++) acc[i][j][k] = 0.0f;

    auto issue = [&](int it) {
        const int s = it % 3, k0 = it * 32;
        #pragma unroll
        for (int i = 0; i < 8; i++) {
            int idx = tid + i * 256;
            int tile = idx >> 9, w = idx & 511, row = w >> 2, ch = w & 3;
            const void* g = (const void*)(srcs[tile] + (size_t)row * FIN + k0 + ch * 8);
            uint32_t d = sbase + s * 32768 + tile * 8192 + tileoff(row, ch);
            CP_ASYNC16(d, g);
        }
        CP_COMMIT();
    };

    issue(0);
    issue(1);

    for (int it = 0; it < NKI; it++) {
        CP_WAIT(1);
        __syncthreads();
        if (it + 2 < NKI) issue(it + 2);
        const uint32_t st = sbase + (it % 3) * 32768;

        #pragma unroll
        for (int ks = 0; ks < 2; ks++) {
            uint32_t ah[2][4], al[2][4];
            #pragma unroll
            for (int mt = 0; mt < 2; mt++) {
                int row = wm + mt * 16 + (lane & 15);
                int ch  = ks * 2 + (lane >> 4);
                uint32_t off = tileoff(row, ch);
                LDSM_X4(ah[mt][0], ah[mt][1], ah[mt][2], ah[mt][3], st + off);
                LDSM_X4(al[mt][0], al[mt][1], al[mt][2], al[mt][3], st + 8192 + off);
            }
            #pragma unroll
            for (int nh = 0; nh < 2; nh++) {
                uint32_t bh[4][2], bl[4][2];
                #pragma unroll
                for (int np = 0; np < 2; np++) {
                    int row = wn + nh * 32 + np * 16 + ((lane >> 4) << 3) + (lane & 7);
                    int ch  = ks * 2 + ((lane >> 3) & 1);
                    uint32_t off = tileoff(row, ch);
                    LDSM_X4(bh[np*2][0], bh[np*2][1], bh[np*2+1][0], bh[np*2+1][1],
                            st + 16384 + off);
                    LDSM_X4(bl[np*2][0], bl[np*2][1], bl[np*2+1][0], bl[np*2+1][1],
                            st + 24576 + off);
                }
                #pragma unroll
                for (int mt = 0; mt < 2; mt++)
                    #pragma unroll
                    for (int nt = 0; nt < 4; nt++) {
                        float* d = acc[mt][nh*4 + nt];
                        MMA16816(d, ah[mt], bh[nt]);
                        MMA16816(d, ah[mt], bl[nt]);
                        MMA16816(d, al[mt], bh[nt]);
                    }
            }
        }
    }

    // epilogue: pick output side by column block
    const bool second = (n0 >= nsplit);
    float* __restrict__ C = second ? C1 : C0;
    const float* __restrict__ bias = second ? bias1 : bias0;
    const int nb = n0 - (second ? nsplit : 0);

    const int g4 = lane >> 2, t4 = lane & 3;
    #pragma unroll
    for (int mt = 0; mt < 2; mt++) {
        #pragma unroll
        for (int nt = 0; nt < 8; nt++) {
            int col = nb + wn + nt * 8 + t4 * 2;
            if (col >= nmax) continue;
            float b0 = bias[col], b1 = bias[col + 1];
            int r0 = m0 + wm + mt * 16 + g4;
            float* d = acc[mt][nt];
            if (r0 < NN) {
                float2 v = make_float2(d[0] + b0, d[1] + b1);
                *(float2*)&C[(size_t)r0 * ldc + col] = v;
            }
            if (r0 + 8 < NN) {
                float2 v = make_float2(d[2] + b0, d[3] + b1);
                *(float2*)&C[(size_t)(r0 + 8) * ldc + col] = v;
            }
        }
    }
}

// ---------------- fused per-node edge phase ----------------
__global__ __launch_bounds__(256)
void node_fused_kernel(const float* __restrict__ att, const float* __restrict__ bias) {
    __shared__ float s_xr[HC];
    __shared__ float s_att[HC];
    __shared__ float s_sc[HH][SC_MAX];

    const int i = blockIdx.x;
    const int tid = threadIdx.x, lane = tid & 31, wid = tid >> 5;
    const int deg = g_deg[i], off = g_off[i];
    int ecnt = deg + 1;
    if (ecnt > SC_MAX) ecnt = SC_MAX;

    #pragma unroll
    for (int c = tid; c < HC; c += 256) {
        s_xr[c]  = g_xr[(size_t)i * HC + c];
        s_att[c] = att[c];
    }
    __syncthreads();

    const int npairs = ecnt * HH;
    for (int p = wid; p < npairs; p += 8) {
        int e = p / HH, h = p % HH;
        int src = (e < deg) ? g_srcs[off + e] : i;
        const float* xlrow = g_xl + (size_t)src * HC + h * CC;
        const float* xr_h  = s_xr + h * CC;
        const float* at_h  = s_att + h * CC;
        float acc = 0.0f;
        #pragma unroll 4
        for (int c = lane; c < CC; c += 32) {
            float v = xlrow[c] + xr_h[c];
            v = (v > 0.0f) ? v : 0.2f * v;
            acc += at_h[c] * v;
        }
        #pragma unroll
        for (int o = 16; o; o >>= 1) acc += __shfl_xor_sync(0xFFFFFFFF, acc, o);
        if (lane == 0) s_sc[h][e] = acc;
    }
    __syncthreads();

    if (wid < HH) {
        float m = -1e30f;
        for (int e = lane; e < ecnt; e += 32) m = fmaxf(m, s_sc[wid][e]);
        #pragma unroll
        for (int o = 16; o; o >>= 1) m = fmaxf(m, __shfl_xor_sync(0xFFFFFFFF, m, o));
        float sum = 0.0f;
        for (int e = lane; e < ecnt; e += 32) {
            float ex = expf(s_sc[wid][e] - m);
            s_sc[wid][e] = ex;
            sum += ex;
        }
        #pragma unroll
        for (int o = 16; o; o >>= 1) sum += __shfl_xor_sync(0xFFFFFFFF, sum, o);
        float inv = 1.0f / (sum + 1e-16f);
        for (int e = lane; e < ecnt; e += 32) s_sc[wid][e] *= inv;
    }
    __syncthreads();

    float a0 = 0.0f, a1 = 0.0f, a2 = 0.0f, a3 = 0.0f;
    for (int e = 0; e < ecnt; e++) {
        int src = (e < deg) ? g_srcs[off + e] : i;
        const float* base = g_xl + (size_t)src * HC;
        #pragma unroll
        for (int h = 0; h < HH; h++) {
            float al = s_sc[h][e];
            const float* row = base + h * CC;
            a0 += al * row[tid];
            a1 += al * row[tid + 256];
            a2 += al * row[tid + 512];
            a3 += al * row[tid + 768];
        }
    }
    const float third = 1.0f / 3.0f;
    float* ho = g_h + (size_t)i * CC;
    ho[tid]       = a0 * third + bias[tid];
    ho[tid + 256] = a1 * third + bias[tid + 256];
    ho[tid + 512] = a2 * third + bias[tid + 512];
    ho[tid + 768] = a3 * third + bias[tid + 768];
}

// convert h -> split bf16 (reuses g_xh/g_xlo)
__global__ void convert_h_kernel() {
    int stride = gridDim.x * blockDim.x;
    for (int i = blockIdx.x * blockDim.x + threadIdx.x; i < MPAD*CC; i += stride) {
        int row = i >> 10;
        float v = (row < NN) ? g_h[i] : 0.0f;
        __nv_bfloat16 h = __float2bfloat16(v);
        g_xh[i]  = h;
        g_xlo[i] = __float2bfloat16(v - __bfloat162float(h));
    }
}

// ---------------- launch ----------------
extern "C" void kernel_launch(void* const* d_in, const int* in_sizes, int n_in,
                              void* d_out, int out_size) {
    const float* x      = (const float*)d_in[0];
    const void*  ei     = d_in[1];
    const float* Wl     = (const float*)d_in[2];
    const float* bl     = (const float*)d_in[3];
    const float* Wr     = (const float*)d_in[4];
    const float* br     = (const float*)d_in[5];
    const float* att    = (const float*)d_in[6];
    const float* bias   = (const float*)d_in[7];
    const float* Wfc    = (const float*)d_in[8];
    const float* bfc    = (const float*)d_in[9];
    const float* exps   = (const float*)d_in[10];
    const float* exps_c = (const float*)d_in[11];
    float* out = (float*)d_out;

    float *p_xl, *p_xr;
    __nv_bfloat16 *p_wth, *p_wtl, *p_wfch, *p_wfcl;
    cudaGetSymbolAddress((void**)&p_xl, g_xl);
    cudaGetSymbolAddress((void**)&p_xr, g_xr);
    cudaGetSymbolAddress((void**)&p_wth, g_wth);
    cudaGetSymbolAddress((void**)&p_wtl, g_wtl);
    cudaGetSymbolAddress((void**)&p_wfch, g_wfch);
    cudaGetSymbolAddress((void**)&p_wfcl, g_wfcl);

    cudaFuncSetAttribute(mma_gemm_kernel, cudaFuncAttributeMaxDynamicSharedMemorySize, SMEM_MMA);

    detect_idx_kernel<<<1, 256>>>((const int*)ei);

    // CSR build
    zero_deg_kernel<<<(NN + 255) / 256, 256>>>();
    histo_kernel<<<(EE + 255) / 256, 256>>>(ei);
    scan_kernel<<<1, 1024>>>();
    scatter_kernel<<<(EE + 255) / 256, 256>>>(ei);

    // split-bf16 conversions
    convert_x_kernel<<<2048, 256>>>(x);
    {
        dim3 bw(32, 8);
        convert_w_kernel<<<dim3(HC/32, FIN/32), bw>>>(Wl, HC, p_wth, p_wtl);
        convert_w_kernel<<<dim3(HC/32, FIN/32), bw>>>(Wr, HC,
            p_wth + (size_t)HC*FIN, p_wtl + (size_t)HC*FIN);
        convert_w_kernel<<<dim3(512/32, CC/32), bw>>>(Wfc, NCLS, p_wfch, p_wfcl);
    }

    // fused projection GEMMs: N = 6144, split at 3072 into g_xl / g_xr
    mma_gemm_kernel<<<dim3(2*HC/128, MPAD/128), 256, SMEM_MMA>>>(
        p_wth, p_wtl, bl, br, p_xl, p_xr, HC, HC, HC);

    // fused edge phase
    node_fused_kernel<<<NN, 256>>>(att, bias);

    // FC readout
    convert_h_kernel<<<2048, 256>>>();
    mma_gemm_kernel<<<dim3(512/128, MPAD/128), 256, SMEM_MMA>>>(
        p_wfch, p_wfcl, bfc, bfc, out, out, NCLS, NCLS, 1 << 30);

    // pass-throughs
    long off = (long)NN * NCLS;
    if (n_in >= 12 && (long)out_size >= off + in_sizes[10] + in_sizes[11]) {
        cudaMemcpyAsync(out + off, exps, (size_t)in_sizes[10] * sizeof(float),
                        cudaMemcpyDeviceToDevice);
        cudaMemcpyAsync(out + off + in_sizes[10], exps_c,
                        (size_t)in_sizes[11] * sizeof(float),
                        cudaMemcpyDeviceToDevice);
    }
}

// round 8
// speedup vs baseline: 6.5322x; 1.7748x over previous
#include <cuda_runtime.h>
#include <cuda_bf16.h>
#include <cuda_fp16.h>
#include <cstdint>
#include <limits.h>

// Problem constants
#define NN   10000
#define FIN  1024
#define HH   3
#define CC   1024
#define HC   (HH*CC)     // 3072
#define NCLS 460
#define EE   100000
#define MPAD 10112       // 79 * 128
#define SC_MAX 352

// ---------------- scratch (device globals) ----------------
__device__ float g_xl[NN*HC];
__device__ float g_xr[NN*HC];
__device__ float g_h[NN*CC];
__device__ int   g_is64;

// CSR
__device__ int g_deg[NN];
__device__ int g_off[NN];
__device__ int g_cursor[NN];
__device__ int g_srcs[EE];

// fp16 operands
__device__ __half g_xh[MPAD*FIN];        // A operand (x, later h)
__device__ __half g_wth[2][HC*FIN];      // [Wl^T ; Wr^T] fp16, contiguous (6144 x 1024)
__device__ __half g_wfch[512*FIN];       // Wfc^T fp16 (zero-padded to 512 rows)

// ---------------- small helpers ----------------
__device__ __forceinline__ void edge_sd(const void* ei, int e, int& s, int& d) {
    if (g_is64) {
        const long long* p = (const long long*)ei;
        s = (int)p[2*e]; d = (int)p[2*e+1];
    } else {
        const int* p = (const int*)ei;
        s = p[2*e]; d = p[2*e+1];
    }
}
__device__ __forceinline__ uint32_t smem_u32(const void* p) {
    uint32_t a;
    asm("{ .reg .u64 t; cvta.to.shared.u64 t, %1; cvt.u32.u64 %0, t; }" : "=r"(a) : "l"(p));
    return a;
}

#define CP_ASYNC16(dst, src) \
    asm volatile("cp.async.cg.shared.global [%0], [%1], 16;" :: "r"(dst), "l"(src))
#define CP_COMMIT() asm volatile("cp.async.commit_group;" ::: "memory")
#define CP_WAIT(n)  asm volatile("cp.async.wait_group %0;" :: "n"(n) : "memory")

#define LDSM_X4(r0, r1, r2, r3, addr) \
    asm volatile("ldmatrix.sync.aligned.m8n8.x4.shared.b16 {%0,%1,%2,%3}, [%4];" \
        : "=r"(r0), "=r"(r1), "=r"(r2), "=r"(r3) : "r"(addr))

#define MMA16816F16(d, a, b) \
    asm volatile("mma.sync.aligned.m16n8k16.row.col.f32.f16.f16.f32 " \
        "{%0,%1,%2,%3},{%4,%5,%6,%7},{%8,%9},{%0,%1,%2,%3};" \
        : "+f"((d)[0]), "+f"((d)[1]), "+f"((d)[2]), "+f"((d)[3]) \
        : "r"((a)[0]), "r"((a)[1]), "r"((a)[2]), "r"((a)[3]), "r"((b)[0]), "r"((b)[1]))

__device__ __forceinline__ uint32_t tileoff(int row, int chunk) {
    return (uint32_t)(row * 64 + ((chunk ^ ((row >> 1) & 3)) << 4));
}

__global__ void detect_idx_kernel(const int* ei) {
    __shared__ int any_nz;
    if (threadIdx.x == 0) any_nz = 0;
    __syncthreads();
    for (int i = threadIdx.x; i < 2048; i += blockDim.x)
        if (ei[2*i + 1] != 0) any_nz = 1;
    __syncthreads();
    if (threadIdx.x == 0) g_is64 = (any_nz == 0) ? 1 : 0;
}

// ---------------- CSR build ----------------
__global__ void zero_deg_kernel() {
    int i = blockIdx.x * blockDim.x + threadIdx.x;
    if (i < NN) g_deg[i] = 0;
}
__global__ void histo_kernel(const void* __restrict__ ei) {
    int e = blockIdx.x * blockDim.x + threadIdx.x;
    if (e >= EE) return;
    int s, d; edge_sd(ei, e, s, d);
    atomicAdd(&g_deg[d], 1);
}
__global__ void scan_kernel() {   // single block, 1024 threads
    __shared__ int s_warp[32];
    __shared__ int s_carry;
    int tid = threadIdx.x, lane = tid & 31, w = tid >> 5;
    if (tid == 0) s_carry = 0;
    __syncthreads();
    for (int base = 0; base < NN; base += 1024) {
        int idx = base + tid;
        int v = (idx < NN) ? g_deg[idx] : 0;
        int x = v;
        #pragma unroll
        for (int o = 1; o < 32; o <<= 1) {
            int y = __shfl_up_sync(0xFFFFFFFF, x, o);
            if (lane >= o) x += y;
        }
        if (lane == 31) s_warp[w] = x;
        __syncthreads();
        if (w == 0) {
            int y = s_warp[lane];
            #pragma unroll
            for (int o = 1; o < 32; o <<= 1) {
                int z = __shfl_up_sync(0xFFFFFFFF, y, o);
                if (lane >= o) y += z;
            }
            s_warp[lane] = y;
        }
        __syncthreads();
        int incl = x + (w > 0 ? s_warp[w - 1] : 0);
        int excl = incl - v + s_carry;
        if (idx < NN) { g_off[idx] = excl; g_cursor[idx] = excl; }
        __syncthreads();
        if (tid == 1023) s_carry += incl;
        __syncthreads();
    }
}
__global__ void scatter_kernel(const void* __restrict__ ei) {
    int e = blockIdx.x * blockDim.x + threadIdx.x;
    if (e >= EE) return;
    int s, d; edge_sd(ei, e, s, d);
    int pos = atomicAdd(&g_cursor[d], 1);
    g_srcs[pos] = s;
}

// ---------------- fp16 conversion ----------------
__global__ void convert_x_kernel(const float* __restrict__ x) {
    int stride = gridDim.x * blockDim.x;
    for (int i = blockIdx.x * blockDim.x + threadIdx.x; i < MPAD*FIN; i += stride) {
        int row = i >> 10;
        float v = (row < NN) ? x[i] : 0.0f;
        g_xh[i] = __float2half_rn(v);
    }
}

// transpose W [K=1024, N] -> Wt [Npad][1024] fp16; zero rows >= N
__global__ void convert_w_kernel(const float* __restrict__ W, int N,
                                 __half* __restrict__ Th) {
    __shared__ float t[32][33];
    int n0 = blockIdx.x * 32, k0 = blockIdx.y * 32;
    int tx = threadIdx.x, ty = threadIdx.y;
    #pragma unroll
    for (int j = 0; j < 32; j += 8) {
        int n = n0 + tx;
        t[ty + j][tx] = (n < N) ? W[(long)(k0 + ty + j) * N + n] : 0.0f;
    }
    __syncthreads();
    #pragma unroll
    for (int j = 0; j < 32; j += 8) {
        long o = (long)(n0 + ty + j) * FIN + k0 + tx;
        Th[o] = __float2half_rn(t[tx][ty + j]);
    }
}

// ---------------- fp16 mma.sync GEMM, 4-stage pipeline ----------------
// C = A(g_xh) @ B^T + bias.  Columns < nsplit -> C0/bias0, >= nsplit -> C1/bias1.
#define NKI (FIN/32)
#define STAGE_B 16384             // 2 tiles x 8KB
#define SMEM_MMA (4*STAGE_B)      // 64KB

__global__ __launch_bounds__(256, 2)
void mma_gemm_kernel(const __half* __restrict__ Bh_g,
                     const float* __restrict__ bias0, const float* __restrict__ bias1,
                     float* __restrict__ C0, float* __restrict__ C1,
                     int ldc, int nmax, int nsplit) {
    extern __shared__ char smem[];
    const uint32_t sbase = smem_u32(smem);
    const int tid = threadIdx.x, lane = tid & 31, wid = tid >> 5;
    const int wm = (wid >> 1) * 32, wn = (wid & 1) * 64;
    const int m0 = blockIdx.y * 128, n0 = blockIdx.x * 128;

    const __half* srcA = g_xh + (size_t)m0 * FIN;
    const __half* srcB = Bh_g + (size_t)n0 * FIN;

    float acc[2][8][4];
    #pragma unroll
    for (int i = 0; i < 2; i++)
        #pragma unroll
        for (int j = 0; j < 8; j++)
            #pragma unroll
            for (int k = 0; k < 4; k++) acc[i][j][k] = 0.0f;

    auto issue = [&](int it) {
        const int s = it & 3, k0 = it * 32;
        #pragma unroll
        for (int i = 0; i < 4; i++) {
            int idx = tid + i * 256;
            int tile = idx >> 9, w = idx & 511, row = w >> 2, ch = w & 3;
            const __half* src = tile ? srcB : srcA;
            const void* g = (const void*)(src + (size_t)row * FIN + k0 + ch * 8);
            uint32_t d = sbase + s * STAGE_B + tile * 8192 + tileoff(row, ch);
            CP_ASYNC16(d, g);
        }
        CP_COMMIT();
    };

    issue(0); issue(1); issue(2);

    for (int it = 0; it < NKI; it++) {
        CP_WAIT(2);
        __syncthreads();
        if (it + 3 < NKI) issue(it + 3);
        const uint32_t st = sbase + (it & 3) * STAGE_B;

        #pragma unroll
        for (int ks = 0; ks < 2; ks++) {
            uint32_t a[2][4];
            #pragma unroll
            for (int mt = 0; mt < 2; mt++) {
                int row = wm + mt * 16 + (lane & 15);
                int ch  = ks * 2 + (lane >> 4);
                LDSM_X4(a[mt][0], a[mt][1], a[mt][2], a[mt][3], st + tileoff(row, ch));
            }
            #pragma unroll
            for (int nh = 0; nh < 2; nh++) {
                uint32_t b[4][2];
                #pragma unroll
                for (int np = 0; np < 2; np++) {
                    int row = wn + nh * 32 + np * 16 + ((lane >> 4) << 3) + (lane & 7);
                    int ch  = ks * 2 + ((lane >> 3) & 1);
                    LDSM_X4(b[np*2][0], b[np*2][1], b[np*2+1][0], b[np*2+1][1],
                            st + 8192 + tileoff(row, ch));
                }
                #pragma unroll
                for (int mt = 0; mt < 2; mt++)
                    #pragma unroll
                    for (int nt = 0; nt < 4; nt++)
                        MMA16816F16(acc[mt][nh*4 + nt], a[mt], b[nt]);
            }
        }
    }

    // epilogue
    const bool second = (n0 >= nsplit);
    float* __restrict__ C = second ? C1 : C0;
    const float* __restrict__ bias = second ? bias1 : bias0;
    const int nb = n0 - (second ? nsplit : 0);

    const int g4 = lane >> 2, t4 = lane & 3;
    #pragma unroll
    for (int mt = 0; mt < 2; mt++) {
        #pragma unroll
        for (int nt = 0; nt < 8; nt++) {
            int col = nb + wn + nt * 8 + t4 * 2;
            if (col >= nmax) continue;
            float b0 = bias[col], b1 = bias[col + 1];
            int r0 = m0 + wm + mt * 16 + g4;
            float* d = acc[mt][nt];
            if (r0 < NN) {
                float2 v = make_float2(d[0] + b0, d[1] + b1);
                *(float2*)&C[(size_t)r0 * ldc + col] = v;
            }
            if (r0 + 8 < NN) {
                float2 v = make_float2(d[2] + b0, d[3] + b1);
                *(float2*)&C[(size_t)(r0 + 8) * ldc + col] = v;
            }
        }
    }
}

// ---------------- fused per-node edge phase ----------------
__global__ __launch_bounds__(256)
void node_fused_kernel(const float* __restrict__ att, const float* __restrict__ bias) {
    __shared__ float s_xr[HC];
    __shared__ float s_att[HC];
    __shared__ float s_sc[HH][SC_MAX];
    __shared__ int   s_src[SC_MAX];

    const int i = blockIdx.x;
    const int tid = threadIdx.x, lane = tid & 31, wid = tid >> 5;
    const int deg = g_deg[i], off = g_off[i];
    int ecnt = deg + 1;
    if (ecnt > SC_MAX) ecnt = SC_MAX;

    #pragma unroll
    for (int c = tid; c < HC; c += 256) {
        s_xr[c]  = g_xr[(size_t)i * HC + c];
        s_att[c] = att[c];
    }
    for (int e = tid; e < ecnt; e += 256)
        s_src[e] = (e < deg) ? g_srcs[off + e] : i;
    __syncthreads();

    // scores: warp per (edge, head) pair
    const int npairs = ecnt * HH;
    for (int p = wid; p < npairs; p += 8) {
        int e = p / HH, h = p % HH;
        int src = s_src[e];
        const float* xlrow = g_xl + (size_t)src * HC + h * CC;
        const float* xr_h  = s_xr + h * CC;
        const float* at_h  = s_att + h * CC;
        float acc = 0.0f;
        #pragma unroll 4
        for (int c = lane; c < CC; c += 32) {
            float v = xlrow[c] + xr_h[c];
            v = (v > 0.0f) ? v : 0.2f * v;
            acc += at_h[c] * v;
        }
        #pragma unroll
        for (int o = 16; o; o >>= 1) acc += __shfl_xor_sync(0xFFFFFFFF, acc, o);
        if (lane == 0) s_sc[h][e] = acc;
    }
    __syncthreads();

    // softmax per head (warps 0..2)
    if (wid < HH) {
        float m = -1e30f;
        for (int e = lane; e < ecnt; e += 32) m = fmaxf(m, s_sc[wid][e]);
        #pragma unroll
        for (int o = 16; o; o >>= 1) m = fmaxf(m, __shfl_xor_sync(0xFFFFFFFF, m, o));
        float sum = 0.0f;
        for (int e = lane; e < ecnt; e += 32) {
            float ex = expf(s_sc[wid][e] - m);
            s_sc[wid][e] = ex;
            sum += ex;
        }
        #pragma unroll
        for (int o = 16; o; o >>= 1) sum += __shfl_xor_sync(0xFFFFFFFF, sum, o);
        float inv = 1.0f / (sum + 1e-16f);
        for (int e = lane; e < ecnt; e += 32) s_sc[wid][e] *= inv;
    }
    __syncthreads();

    // aggregate + head mean + bias: thread owns 4 contiguous channels [4t, 4t+4)
    float4 a = make_float4(0.f, 0.f, 0.f, 0.f);
    for (int e = 0; e < ecnt; e++) {
        const float4* base = (const float4*)(g_xl + (size_t)s_src[e] * HC);
        #pragma unroll
        for (int h = 0; h < HH; h++) {
            float al = s_sc[h][e];
            float4 v = base[h * 256 + tid];
            a.x += al * v.x; a.y += al * v.y; a.z += al * v.z; a.w += al * v.w;
        }
    }
    const float third = 1.0f / 3.0f;
    float4 bv = ((const float4*)bias)[tid];
    float4 o4 = make_float4(a.x * third + bv.x, a.y * third + bv.y,
                            a.z * third + bv.z, a.w * third + bv.w);
    ((float4*)(g_h + (size_t)i * CC))[tid] = o4;
}

// convert h -> fp16 (reuses g_xh)
__global__ void convert_h_kernel() {
    int stride = gridDim.x * blockDim.x;
    for (int i = blockIdx.x * blockDim.x + threadIdx.x; i < MPAD*CC; i += stride) {
        int row = i >> 10;
        float v = (row < NN) ? g_h[i] : 0.0f;
        g_xh[i] = __float2half_rn(v);
    }
}

// ---------------- launch ----------------
extern "C" void kernel_launch(void* const* d_in, const int* in_sizes, int n_in,
                              void* d_out, int out_size) {
    const float* x      = (const float*)d_in[0];
    const void*  ei     = d_in[1];
    const float* Wl     = (const float*)d_in[2];
    const float* bl     = (const float*)d_in[3];
    const float* Wr     = (const float*)d_in[4];
    const float* br     = (const float*)d_in[5];
    const float* att    = (const float*)d_in[6];
    const float* bias   = (const float*)d_in[7];
    const float* Wfc    = (const float*)d_in[8];
    const float* bfc    = (const float*)d_in[9];
    const float* exps   = (const float*)d_in[10];
    const float* exps_c = (const float*)d_in[11];
    float* out = (float*)d_out;

    float *p_xl, *p_xr;
    __half *p_wth, *p_wfch;
    cudaGetSymbolAddress((void**)&p_xl, g_xl);
    cudaGetSymbolAddress((void**)&p_xr, g_xr);
    cudaGetSymbolAddress((void**)&p_wth, g_wth);
    cudaGetSymbolAddress((void**)&p_wfch, g_wfch);

    cudaFuncSetAttribute(mma_gemm_kernel, cudaFuncAttributeMaxDynamicSharedMemorySize, SMEM_MMA);

    detect_idx_kernel<<<1, 256>>>((const int*)ei);

    // CSR build
    zero_deg_kernel<<<(NN + 255) / 256, 256>>>();
    histo_kernel<<<(EE + 255) / 256, 256>>>(ei);
    scan_kernel<<<1, 1024>>>();
    scatter_kernel<<<(EE + 255) / 256, 256>>>(ei);

    // fp16 conversions
    convert_x_kernel<<<2048, 256>>>(x);
    {
        dim3 bw(32, 8);
        convert_w_kernel<<<dim3(HC/32, FIN/32), bw>>>(Wl, HC, p_wth);
        convert_w_kernel<<<dim3(HC/32, FIN/32), bw>>>(Wr, HC, p_wth + (size_t)HC*FIN);
        convert_w_kernel<<<dim3(512/32, CC/32), bw>>>(Wfc, NCLS, p_wfch);
    }

    // fused projection GEMMs: N = 6144, split at 3072 into g_xl / g_xr
    mma_gemm_kernel<<<dim3(2*HC/128, MPAD/128), 256, SMEM_MMA>>>(
        p_wth, bl, br, p_xl, p_xr, HC, HC, HC);

    // fused edge phase
    node_fused_kernel<<<NN, 256>>>(att, bias);

    // FC readout
    convert_h_kernel<<<2048, 256>>>();
    mma_gemm_kernel<<<dim3(512/128, MPAD/128), 256, SMEM_MMA>>>(
        p_wfch, bfc, bfc, out, out, NCLS, NCLS, 1 << 30);

    // pass-throughs
    long off = (long)NN * NCLS;
    if (n_in >= 12 && (long)out_size >= off + in_sizes[10] + in_sizes[11]) {
        cudaMemcpyAsync(out + off, exps, (size_t)in_sizes[10] * sizeof(float),
                        cudaMemcpyDeviceToDevice);
        cudaMemcpyAsync(out + off + in_sizes[10], exps_c,
                        (size_t)in_sizes[11] * sizeof(float),
                        cudaMemcpyDeviceToDevice);
    }
}

// round 9
// speedup vs baseline: 7.9309x; 1.2141x over previous
#include <cuda_runtime.h>
#include <cuda_bf16.h>
#include <cuda_fp16.h>
#include <cstdint>
#include <limits.h>

// Problem constants
#define NN   10000
#define FIN  1024
#define HH   3
#define CC   1024
#define HC   (HH*CC)     // 3072
#define NCLS 460
#define EE   100000
#define MPAD 10112       // 79 * 128
#define SC_MAX 352

// ---------------- scratch (device globals) ----------------
__device__ __half g_xl[NN*HC];           // fp16 projections
__device__ __half g_xr[NN*HC];
__device__ int    g_is64;

// CSR
__device__ int g_deg[NN];
__device__ int g_off[NN];
__device__ int g_cursor[NN];
__device__ int g_srcs[EE];

// fp16 operands
__device__ __half g_xh[MPAD*FIN];        // A operand (x for projections, then h for FC)
__device__ __half g_wth[2][HC*FIN];      // [Wl^T ; Wr^T] fp16 (6144 x 1024)
__device__ __half g_wfch[512*FIN];       // Wfc^T fp16 (zero-padded to 512 rows)

// ---------------- small helpers ----------------
__device__ __forceinline__ void edge_sd(const void* ei, int e, int& s, int& d) {
    if (g_is64) {
        const long long* p = (const long long*)ei;
        s = (int)p[2*e]; d = (int)p[2*e+1];
    } else {
        const int* p = (const int*)ei;
        s = p[2*e]; d = p[2*e+1];
    }
}
__device__ __forceinline__ uint32_t smem_u32(const void* p) {
    uint32_t a;
    asm("{ .reg .u64 t; cvta.to.shared.u64 t, %1; cvt.u32.u64 %0, t; }" : "=r"(a) : "l"(p));
    return a;
}

#define CP_ASYNC16(dst, src) \
    asm volatile("cp.async.cg.shared.global [%0], [%1], 16;" :: "r"(dst), "l"(src))
#define CP_COMMIT() asm volatile("cp.async.commit_group;" ::: "memory")
#define CP_WAIT(n)  asm volatile("cp.async.wait_group %0;" :: "n"(n) : "memory")

#define LDSM_X4(r0, r1, r2, r3, addr) \
    asm volatile("ldmatrix.sync.aligned.m8n8.x4.shared.b16 {%0,%1,%2,%3}, [%4];" \
        : "=r"(r0), "=r"(r1), "=r"(r2), "=r"(r3) : "r"(addr))

#define MMA16816F16(d, a, b) \
    asm volatile("mma.sync.aligned.m16n8k16.row.col.f32.f16.f16.f32 " \
        "{%0,%1,%2,%3},{%4,%5,%6,%7},{%8,%9},{%0,%1,%2,%3};" \
        : "+f"((d)[0]), "+f"((d)[1]), "+f"((d)[2]), "+f"((d)[3]) \
        : "r"((a)[0]), "r"((a)[1]), "r"((a)[2]), "r"((a)[3]), "r"((b)[0]), "r"((b)[1]))

__device__ __forceinline__ uint32_t tileoff(int row, int chunk) {
    return (uint32_t)(row * 64 + ((chunk ^ ((row >> 1) & 3)) << 4));
}

__global__ void detect_idx_kernel(const int* ei) {
    __shared__ int any_nz;
    if (threadIdx.x == 0) any_nz = 0;
    __syncthreads();
    for (int i = threadIdx.x; i < 2048; i += blockDim.x)
        if (ei[2*i + 1] != 0) any_nz = 1;
    __syncthreads();
    if (threadIdx.x == 0) g_is64 = (any_nz == 0) ? 1 : 0;
}

// ---------------- CSR build ----------------
__global__ void zero_deg_kernel() {
    int i = blockIdx.x * blockDim.x + threadIdx.x;
    if (i < NN) g_deg[i] = 0;
}
__global__ void histo_kernel(const void* __restrict__ ei) {
    int e = blockIdx.x * blockDim.x + threadIdx.x;
    if (e >= EE) return;
    int s, d; edge_sd(ei, e, s, d);
    atomicAdd(&g_deg[d], 1);
}
__global__ void scan_kernel() {   // single block, 1024 threads
    __shared__ int s_warp[32];
    __shared__ int s_carry;
    int tid = threadIdx.x, lane = tid & 31, w = tid >> 5;
    if (tid == 0) s_carry = 0;
    __syncthreads();
    for (int base = 0; base < NN; base += 1024) {
        int idx = base + tid;
        int v = (idx < NN) ? g_deg[idx] : 0;
        int x = v;
        #pragma unroll
        for (int o = 1; o < 32; o <<= 1) {
            int y = __shfl_up_sync(0xFFFFFFFF, x, o);
            if (lane >= o) x += y;
        }
        if (lane == 31) s_warp[w] = x;
        __syncthreads();
        if (w == 0) {
            int y = s_warp[lane];
            #pragma unroll
            for (int o = 1; o < 32; o <<= 1) {
                int z = __shfl_up_sync(0xFFFFFFFF, y, o);
                if (lane >= o) y += z;
            }
            s_warp[lane] = y;
        }
        __syncthreads();
        int incl = x + (w > 0 ? s_warp[w - 1] : 0);
        int excl = incl - v + s_carry;
        if (idx < NN) { g_off[idx] = excl; g_cursor[idx] = excl; }
        __syncthreads();
        if (tid == 1023) s_carry += incl;
        __syncthreads();
    }
}
__global__ void scatter_kernel(const void* __restrict__ ei) {
    int e = blockIdx.x * blockDim.x + threadIdx.x;
    if (e >= EE) return;
    int s, d; edge_sd(ei, e, s, d);
    int pos = atomicAdd(&g_cursor[d], 1);
    g_srcs[pos] = s;
}

// ---------------- fp16 conversion ----------------
__global__ void convert_x_kernel(const float* __restrict__ x) {
    int stride = gridDim.x * blockDim.x;
    for (int i = blockIdx.x * blockDim.x + threadIdx.x; i < MPAD*FIN; i += stride) {
        int row = i >> 10;
        float v = (row < NN) ? x[i] : 0.0f;
        g_xh[i] = __float2half_rn(v);
    }
}

// transpose W [K=1024, N] -> Wt [Npad][1024] fp16; zero rows >= N
__global__ void convert_w_kernel(const float* __restrict__ W, int N,
                                 __half* __restrict__ Th) {
    __shared__ float t[32][33];
    int n0 = blockIdx.x * 32, k0 = blockIdx.y * 32;
    int tx = threadIdx.x, ty = threadIdx.y;
    #pragma unroll
    for (int j = 0; j < 32; j += 8) {
        int n = n0 + tx;
        t[ty + j][tx] = (n < N) ? W[(long)(k0 + ty + j) * N + n] : 0.0f;
    }
    __syncthreads();
    #pragma unroll
    for (int j = 0; j < 32; j += 8) {
        long o = (long)(n0 + ty + j) * FIN + k0 + tx;
        Th[o] = __float2half_rn(t[tx][ty + j]);
    }
}

// ---------------- fp16 mma.sync GEMM, 4-stage pipeline ----------------
// C = A(g_xh) @ B^T + bias.  Columns < nsplit -> C0/bias0, >= nsplit -> C1/bias1.
// HALF_OUT: store __half results; else fp32.
#define NKI (FIN/32)
#define STAGE_B 16384             // 2 tiles x 8KB
#define SMEM_MMA (4*STAGE_B)      // 64KB

template<int HALF_OUT>
__global__ __launch_bounds__(256, 2)
void mma_gemm_kernel(const __half* __restrict__ Bh_g,
                     const float* __restrict__ bias0, const float* __restrict__ bias1,
                     void* __restrict__ C0v, void* __restrict__ C1v,
                     int ldc, int nmax, int nsplit) {
    extern __shared__ char smem[];
    const uint32_t sbase = smem_u32(smem);
    const int tid = threadIdx.x, lane = tid & 31, wid = tid >> 5;
    const int wm = (wid >> 1) * 32, wn = (wid & 1) * 64;
    const int m0 = blockIdx.y * 128, n0 = blockIdx.x * 128;

    const __half* srcA = g_xh + (size_t)m0 * FIN;
    const __half* srcB = Bh_g + (size_t)n0 * FIN;

    float acc[2][8][4];
    #pragma unroll
    for (int i = 0; i < 2; i++)
        #pragma unroll
        for (int j = 0; j < 8; j++)
            #pragma unroll
            for (int k = 0; k < 4; k++) acc[i][j][k] = 0.0f;

    auto issue = [&](int it) {
        const int s = it & 3, k0 = it * 32;
        #pragma unroll
        for (int i = 0; i < 4; i++) {
            int idx = tid + i * 256;
            int tile = idx >> 9, w = idx & 511, row = w >> 2, ch = w & 3;
            const __half* src = tile ? srcB : srcA;
            const void* g = (const void*)(src + (size_t)row * FIN + k0 + ch * 8);
            uint32_t d = sbase + s * STAGE_B + tile * 8192 + tileoff(row, ch);
            CP_ASYNC16(d, g);
        }
        CP_COMMIT();
    };

    issue(0); issue(1); issue(2);

    for (int it = 0; it < NKI; it++) {
        CP_WAIT(2);
        __syncthreads();
        if (it + 3 < NKI) issue(it + 3);
        const uint32_t st = sbase + (it & 3) * STAGE_B;

        #pragma unroll
        for (int ks = 0; ks < 2; ks++) {
            uint32_t a[2][4];
            #pragma unroll
            for (int mt = 0; mt < 2; mt++) {
                int row = wm + mt * 16 + (lane & 15);
                int ch  = ks * 2 + (lane >> 4);
                LDSM_X4(a[mt][0], a[mt][1], a[mt][2], a[mt][3], st + tileoff(row, ch));
            }
            #pragma unroll
            for (int nh = 0; nh < 2; nh++) {
                uint32_t b[4][2];
                #pragma unroll
                for (int np = 0; np < 2; np++) {
                    int row = wn + nh * 32 + np * 16 + ((lane >> 4) << 3) + (lane & 7);
                    int ch  = ks * 2 + ((lane >> 3) & 1);
                    LDSM_X4(b[np*2][0], b[np*2][1], b[np*2+1][0], b[np*2+1][1],
                            st + 8192 + tileoff(row, ch));
                }
                #pragma unroll
                for (int mt = 0; mt < 2; mt++)
                    #pragma unroll
                    for (int nt = 0; nt < 4; nt++)
                        MMA16816F16(acc[mt][nh*4 + nt], a[mt], b[nt]);
            }
        }
    }

    // epilogue
    const bool second = (n0 >= nsplit);
    const float* __restrict__ bias = second ? bias1 : bias0;
    void* Cv = second ? C1v : C0v;
    const int nb = n0 - (second ? nsplit : 0);

    const int g4 = lane >> 2, t4 = lane & 3;
    #pragma unroll
    for (int mt = 0; mt < 2; mt++) {
        #pragma unroll
        for (int nt = 0; nt < 8; nt++) {
            int col = nb + wn + nt * 8 + t4 * 2;
            if (col >= nmax) continue;
            float b0 = bias[col], b1 = bias[col + 1];
            int r0 = m0 + wm + mt * 16 + g4;
            float* d = acc[mt][nt];
            if (HALF_OUT) {
                __half* C = (__half*)Cv;
                if (r0 < NN)
                    *(__half2*)&C[(size_t)r0 * ldc + col] = __floats2half2_rn(d[0] + b0, d[1] + b1);
                if (r0 + 8 < NN)
                    *(__half2*)&C[(size_t)(r0 + 8) * ldc + col] = __floats2half2_rn(d[2] + b0, d[3] + b1);
            } else {
                float* C = (float*)Cv;
                if (r0 < NN)
                    *(float2*)&C[(size_t)r0 * ldc + col] = make_float2(d[0] + b0, d[1] + b1);
                if (r0 + 8 < NN)
                    *(float2*)&C[(size_t)(r0 + 8) * ldc + col] = make_float2(d[2] + b0, d[3] + b1);
            }
        }
    }
}

// ---------------- fused per-node edge phase (fp16 inputs, fp32 math) --------
// Writes final h row (head-mean + bias) as fp16 straight into g_xh (FC input).
__global__ __launch_bounds__(256)
void node_fused_kernel(const float* __restrict__ att, const float* __restrict__ bias) {
    __shared__ float s_xr[HC];
    __shared__ float s_att[HC];
    __shared__ float s_sc[HH][SC_MAX];
    __shared__ int   s_src[SC_MAX];

    const int i = blockIdx.x;
    const int tid = threadIdx.x, lane = tid & 31, wid = tid >> 5;
    const int deg = g_deg[i], off = g_off[i];
    int ecnt = deg + 1;
    if (ecnt > SC_MAX) ecnt = SC_MAX;

    // load xr row (fp16 -> fp32 smem) and att
    {
        const __half2* xr2 = (const __half2*)(g_xr + (size_t)i * HC);
        #pragma unroll
        for (int c = tid; c < HC/2; c += 256) {
            float2 v = __half22float2(xr2[c]);
            s_xr[2*c] = v.x; s_xr[2*c+1] = v.y;
        }
        #pragma unroll
        for (int c = tid; c < HC; c += 256) s_att[c] = att[c];
    }
    for (int e = tid; e < ecnt; e += 256)
        s_src[e] = (e < deg) ? g_srcs[off + e] : i;
    __syncthreads();

    // scores: warp per (edge, head) pair
    const int npairs = ecnt * HH;
    for (int p = wid; p < npairs; p += 8) {
        int e = p / HH, h = p % HH;
        int src = s_src[e];
        const __half2* xl2 = (const __half2*)(g_xl + (size_t)src * HC + h * CC);
        const float* xr_h  = s_xr + h * CC;
        const float* at_h  = s_att + h * CC;
        float acc = 0.0f;
        #pragma unroll 4
        for (int c = lane; c < CC/2; c += 32) {
            float2 v = __half22float2(xl2[c]);
            float u0 = v.x + xr_h[2*c],   u1 = v.y + xr_h[2*c+1];
            u0 = (u0 > 0.0f) ? u0 : 0.2f * u0;
            u1 = (u1 > 0.0f) ? u1 : 0.2f * u1;
            acc += at_h[2*c] * u0 + at_h[2*c+1] * u1;
        }
        #pragma unroll
        for (int o = 16; o; o >>= 1) acc += __shfl_xor_sync(0xFFFFFFFF, acc, o);
        if (lane == 0) s_sc[h][e] = acc;
    }
    __syncthreads();

    // softmax per head (warps 0..2)
    if (wid < HH) {
        float m = -1e30f;
        for (int e = lane; e < ecnt; e += 32) m = fmaxf(m, s_sc[wid][e]);
        #pragma unroll
        for (int o = 16; o; o >>= 1) m = fmaxf(m, __shfl_xor_sync(0xFFFFFFFF, m, o));
        float sum = 0.0f;
        for (int e = lane; e < ecnt; e += 32) {
            float ex = expf(s_sc[wid][e] - m);
            s_sc[wid][e] = ex;
            sum += ex;
        }
        #pragma unroll
        for (int o = 16; o; o >>= 1) sum += __shfl_xor_sync(0xFFFFFFFF, sum, o);
        float inv = 1.0f / (sum + 1e-16f);
        for (int e = lane; e < ecnt; e += 32) s_sc[wid][e] *= inv;
    }
    __syncthreads();

    // aggregate + head mean + bias: thread owns channels [4t, 4t+4)
    float a0 = 0.f, a1 = 0.f, a2 = 0.f, a3 = 0.f;
    for (int e = 0; e < ecnt; e++) {
        const uint2* base = (const uint2*)(g_xl + (size_t)s_src[e] * HC);
        #pragma unroll
        for (int h = 0; h < HH; h++) {
            float al = s_sc[h][e];
            uint2 p = base[h * 256 + tid];          // 4 halves
            float2 lo = __half22float2(*(__half2*)&p.x);
            float2 hi = __half22float2(*(__half2*)&p.y);
            a0 += al * lo.x; a1 += al * lo.y; a2 += al * hi.x; a3 += al * hi.y;
        }
    }
    const float third = 1.0f / 3.0f;
    float4 bv = ((const float4*)bias)[tid];
    __half2 o0 = __floats2half2_rn(a0 * third + bv.x, a1 * third + bv.y);
    __half2 o1 = __floats2half2_rn(a2 * third + bv.z, a3 * third + bv.w);
    uint2 ov = make_uint2(*(uint32_t*)&o0, *(uint32_t*)&o1);
    ((uint2*)(g_xh + (size_t)i * CC))[tid] = ov;    // h row, fp16, ready for FC
}

// ---------------- launch ----------------
extern "C" void kernel_launch(void* const* d_in, const int* in_sizes, int n_in,
                              void* d_out, int out_size) {
    const float* x      = (const float*)d_in[0];
    const void*  ei     = d_in[1];
    const float* Wl     = (const float*)d_in[2];
    const float* bl     = (const float*)d_in[3];
    const float* Wr     = (const float*)d_in[4];
    const float* br     = (const float*)d_in[5];
    const float* att    = (const float*)d_in[6];
    const float* bias   = (const float*)d_in[7];
    const float* Wfc    = (const float*)d_in[8];
    const float* bfc    = (const float*)d_in[9];
    const float* exps   = (const float*)d_in[10];
    const float* exps_c = (const float*)d_in[11];
    float* out = (float*)d_out;

    __half *p_xl, *p_xr, *p_wth, *p_wfch;
    cudaGetSymbolAddress((void**)&p_xl, g_xl);
    cudaGetSymbolAddress((void**)&p_xr, g_xr);
    cudaGetSymbolAddress((void**)&p_wth, g_wth);
    cudaGetSymbolAddress((void**)&p_wfch, g_wfch);

    cudaFuncSetAttribute(mma_gemm_kernel<1>, cudaFuncAttributeMaxDynamicSharedMemorySize, SMEM_MMA);
    cudaFuncSetAttribute(mma_gemm_kernel<0>, cudaFuncAttributeMaxDynamicSharedMemorySize, SMEM_MMA);

    detect_idx_kernel<<<1, 256>>>((const int*)ei);

    // CSR build
    zero_deg_kernel<<<(NN + 255) / 256, 256>>>();
    histo_kernel<<<(EE + 255) / 256, 256>>>(ei);
    scan_kernel<<<1, 1024>>>();
    scatter_kernel<<<(EE + 255) / 256, 256>>>(ei);

    // fp16 conversions
    convert_x_kernel<<<2048, 256>>>(x);
    {
        dim3 bw(32, 8);
        convert_w_kernel<<<dim3(HC/32, FIN/32), bw>>>(Wl, HC, p_wth);
        convert_w_kernel<<<dim3(HC/32, FIN/32), bw>>>(Wr, HC, p_wth + (size_t)HC*FIN);
        convert_w_kernel<<<dim3(512/32, CC/32), bw>>>(Wfc, NCLS, p_wfch);
    }

    // fused projection GEMMs: N = 6144, split at 3072 into g_xl / g_xr (fp16 out)
    mma_gemm_kernel<1><<<dim3(2*HC/128, MPAD/128), 256, SMEM_MMA>>>(
        p_wth, bl, br, p_xl, p_xr, HC, HC, HC);

    // fused edge phase; writes fp16 h directly into g_xh
    node_fused_kernel<<<NN, 256>>>(att, bias);

    // FC readout (fp32 out)
    mma_gemm_kernel<0><<<dim3(512/128, MPAD/128), 256, SMEM_MMA>>>(
        p_wfch, bfc, bfc, out, out, NCLS, NCLS, 1 << 30);

    // pass-throughs
    long off = (long)NN * NCLS;
    if (n_in >= 12 && (long)out_size >= off + in_sizes[10] + in_sizes[11]) {
        cudaMemcpyAsync(out + off, exps, (size_t)in_sizes[10] * sizeof(float),
                        cudaMemcpyDeviceToDevice);
        cudaMemcpyAsync(out + off + in_sizes[10], exps_c,
                        (size_t)in_sizes[11] * sizeof(float),
                        cudaMemcpyDeviceToDevice);
    }
}